// round 4
// baseline (speedup 1.0000x reference)
#include <cuda_runtime.h>
#include <cuda_bf16.h>
#include <cstdint>

// ---------------------------------------------------------------------------
// Problem constants
// ---------------------------------------------------------------------------
static constexpr int VOCAB = 32000;
static constexpr int DIMS  = 1024;
static constexpr int BB    = 2;
static constexpr int LL    = 2048;
static constexpr int MROWS = BB * LL;          // 4096

// Scratch (static device globals: allocation-free)
__device__ float g_e  [MROWS * DIMS];          // tf32-rounded embeddings (A of GEMM1)
__device__ float g_V  [MROWS * DIMS];          // GEMM1 output (fp32)
__device__ float g_avg[MROWS * DIMS];          // tf32-rounded cummean (A of GEMM2)
__device__ float g_wv [DIMS * DIMS];           // tf32-rounded W_V
__device__ float g_wo [VOCAB * DIMS];          // tf32-rounded W_out
__device__ int   g_is64;

// ---------------------------------------------------------------------------
// PTX helpers (base sm_100-compatible: cp.async + ldmatrix + mma.sync)
// ---------------------------------------------------------------------------
__device__ __forceinline__ uint32_t smem_u32(const void* p) {
    uint32_t a;
    asm("{ .reg .u64 t; cvta.to.shared.u64 t, %1; cvt.u32.u64 %0, t; }" : "=r"(a) : "l"(p));
    return a;
}

#define CP_ASYNC16(dst, src) \
    asm volatile("cp.async.cg.shared.global [%0], [%1], 16;" :: "r"(dst), "l"(src) : "memory")
#define CP_COMMIT() asm volatile("cp.async.commit_group;" ::: "memory")
#define CP_WAIT1()  asm volatile("cp.async.wait_group 1;" ::: "memory")

__device__ __forceinline__ void ldsm_x4(uint32_t* r, uint32_t addr) {
    asm volatile("ldmatrix.sync.aligned.m8n8.x4.shared.b16 {%0,%1,%2,%3}, [%4];"
                 : "=r"(r[0]), "=r"(r[1]), "=r"(r[2]), "=r"(r[3]) : "r"(addr));
}

__device__ __forceinline__ void mma_tf32(float* c, const uint32_t* a,
                                         uint32_t b0, uint32_t b1) {
    asm volatile(
        "mma.sync.aligned.m16n8k8.row.col.f32.tf32.tf32.f32 "
        "{%0,%1,%2,%3}, {%4,%5,%6,%7}, {%8,%9}, {%0,%1,%2,%3};"
        : "+f"(c[0]), "+f"(c[1]), "+f"(c[2]), "+f"(c[3])
        : "r"(a[0]), "r"(a[1]), "r"(a[2]), "r"(a[3]), "r"(b0), "r"(b1));
}

// cvt.rna.tf32.f32: destination must be a .b32 register (ptxas rejects .f32 dst)
__device__ __forceinline__ float tf32_rna(float x) {
    uint32_t r;
    asm("cvt.rna.tf32.f32 %0, %1;" : "=r"(r) : "f"(x));
    return __uint_as_float(r);
}

// ---------------------------------------------------------------------------
// GEMM: C[M,N] = A[M,K] * B[N,K]^T (+bias), tf32 mma.sync, fp32 accumulate.
// CTA tile 128(M) x 256(N) x 32(K); 8 warps (2x4) of 64x64; 3-stage cp.async.
// SMEM rows padded to 144B: conflict-free cp.async stores AND ldmatrix reads.
// ---------------------------------------------------------------------------
static constexpr int MT = 128;
static constexpr int NT = 256;
static constexpr int KC = 32;                      // floats of K per chunk (128B/row)
static constexpr int STAGES = 3;
static constexpr int ROWB = 144;                   // padded row stride in bytes
static constexpr int A_BYTES = MT * ROWB;          // 18432
static constexpr int B_BYTES = NT * ROWB;          // 36864
static constexpr int BUF     = A_BYTES + B_BYTES;  // 55296
static constexpr int SMEM_TOTAL = STAGES * BUF;    // 165888

__device__ __forceinline__ void load_chunk(uint32_t bufb,
                                           const float* __restrict__ A,
                                           const float* __restrict__ Bm,
                                           int mbase, int nbase, int K, int kc, int tid) {
    const int kofs = kc * KC;
    // A: 128 rows x 8 x 16B chunks = 1024 -> 4 per thread
#pragma unroll
    for (int i = 0; i < 4; i++) {
        int j = tid + (i << 8);
        int r = j >> 3, s = j & 7;
        const float* src = A + (size_t)(mbase + r) * K + kofs + s * 4;
        CP_ASYNC16(bufb + (uint32_t)(r * ROWB + s * 16), src);
    }
    // B: 256 rows x 8 chunks = 2048 -> 8 per thread
#pragma unroll
    for (int i = 0; i < 8; i++) {
        int j = tid + (i << 8);
        int r = j >> 3, s = j & 7;
        const float* src = Bm + (size_t)(nbase + r) * K + kofs + s * 4;
        CP_ASYNC16(bufb + (uint32_t)A_BYTES + (uint32_t)(r * ROWB + s * 16), src);
    }
}

__global__ void __launch_bounds__(256, 1)
gemm_tf32_mma(const float* __restrict__ A, const float* __restrict__ Bm,
              const float* __restrict__ bias, float* __restrict__ C,
              int M, int N, int K) {
    extern __shared__ __align__(16) char smem[];
    const uint32_t sb = smem_u32(smem);
    const int tid = threadIdx.x;
    const int wid = tid >> 5;
    const int l   = tid & 31;
    const int wm  = wid >> 2;          // 0..1  (M warp row, 64 rows each)
    const int wn  = wid & 3;           // 0..3  (N warp col, 64 cols each)
    const int mbase = blockIdx.y * MT;
    const int nbase = blockIdx.x * NT;

    // ldmatrix per-lane source row/half: lanes 0-7 m0, 8-15 m1, 16-23 m2, 24-31 m3
    const int     lrow = (l & 7) + ((l >> 3) & 1) * 8;
    const uint32_t lhi = (uint32_t)((l >> 4) * 16);
    const uint32_t a_lane = (uint32_t)((wm * 64 + lrow) * ROWB) + lhi;
    const uint32_t b_lane = (uint32_t)A_BYTES + (uint32_t)((wn * 64 + lrow) * ROWB) + lhi;

    float c[4][8][4];
#pragma unroll
    for (int mt = 0; mt < 4; mt++)
#pragma unroll
        for (int nt = 0; nt < 8; nt++)
#pragma unroll
            for (int q = 0; q < 4; q++) c[mt][nt][q] = 0.0f;

    const int nch = K / KC;

    // prologue: prefetch 2 chunks
    load_chunk(sb, A, Bm, mbase, nbase, K, 0, tid);
    CP_COMMIT();
    load_chunk(sb + BUF, A, Bm, mbase, nbase, K, 1, tid);
    CP_COMMIT();

    uint32_t slot = 0;  // slot of chunk kc
    for (int kc = 0; kc < nch; kc++) {
        CP_WAIT1();                    // chunk kc resident
        __syncthreads();
        const uint32_t bufb = sb + slot * BUF;
        // issue chunk kc+2 into the slot consumed at kc-1
        if (kc + 2 < nch) {
            uint32_t ws = slot + 2; if (ws >= STAGES) ws -= STAGES;
            load_chunk(sb + ws * BUF, A, Bm, mbase, nbase, K, kc + 2, tid);
        }
        CP_COMMIT();                   // commit every iter (keeps group count aligned)

#pragma unroll
        for (int ks = 0; ks < 4; ks++) {
            const uint32_t boff = (uint32_t)(ks * 32);
            uint32_t a[4][4];
#pragma unroll
            for (int mt = 0; mt < 4; mt++)
                ldsm_x4(a[mt], bufb + a_lane + (uint32_t)(mt * 16 * ROWB) + boff);
            uint32_t b[4][4];          // per pair: {b0_even, b0_odd, b1_even, b1_odd}
#pragma unroll
            for (int np = 0; np < 4; np++)
                ldsm_x4(b[np], bufb + b_lane + (uint32_t)(np * 16 * ROWB) + boff);
#pragma unroll
            for (int mt = 0; mt < 4; mt++)
#pragma unroll
                for (int nt = 0; nt < 8; nt++) {
                    const int np = nt >> 1, od = nt & 1;
                    mma_tf32(c[mt][nt], a[mt], b[np][od], b[np][2 + od]);
                }
        }
        slot++; if (slot >= STAGES) slot = 0;
        __syncthreads();               // compute done before slot reuse next iter
    }

    // Epilogue: c[mt][nt]: rows = mbase+wm*64+mt*16+{g,g+8}, cols = nbase+wn*64+nt*8+2t+{0,1}
    const int g = l >> 2, t = l & 3;
    const int row0 = mbase + wm * 64 + g;
    const int colb = nbase + wn * 64 + t * 2;
#pragma unroll
    for (int nt = 0; nt < 8; nt++) {
        float2 bv = make_float2(0.0f, 0.0f);
        if (bias) bv = *reinterpret_cast<const float2*>(bias + colb + nt * 8);
#pragma unroll
        for (int mt = 0; mt < 4; mt++) {
            const int r = row0 + mt * 16;
            float2 v0 = make_float2(c[mt][nt][0] + bv.x, c[mt][nt][1] + bv.y);
            float2 v1 = make_float2(c[mt][nt][2] + bv.x, c[mt][nt][3] + bv.y);
            *reinterpret_cast<float2*>(C + (size_t)r * N + colb + nt * 8)       = v0;
            *reinterpret_cast<float2*>(C + (size_t)(r + 8) * N + colb + nt * 8) = v1;
        }
    }
}

// ---------------------------------------------------------------------------
// Small kernels
// ---------------------------------------------------------------------------
__global__ void detect_kernel(const void* seq) {
    __shared__ int ok;
    if (threadIdx.x == 0) ok = 1;
    __syncthreads();
    const long long* p = (const long long*)seq;   // reads 16KB <= int32 buffer size
    for (int i = threadIdx.x; i < MROWS / 2; i += blockDim.x) {
        long long v = p[i];
        if (v < 0 || v >= VOCAB) ok = 0;
    }
    __syncthreads();
    if (threadIdx.x == 0) g_is64 = ok;
}

// gather + tf32 round (A of GEMM1)
__global__ void gather_kernel(const void* seq, const float* __restrict__ emb,
                              float* __restrict__ e) {
    const int row  = blockIdx.x * 8 + (threadIdx.x >> 5);
    const int lane = threadIdx.x & 31;
    long long tok;
    if (g_is64) tok = ((const long long*)seq)[row];
    else        tok = (long long)((const int*)seq)[row];
    const float4* s = (const float4*)(emb + (size_t)tok * DIMS);
    float4*       d = (float4*)(e + (size_t)row * DIMS);
#pragma unroll
    for (int i = 0; i < 8; i++) {
        float4 v = s[lane + 32 * i];
        v.x = tf32_rna(v.x); v.y = tf32_rna(v.y);
        v.z = tf32_rna(v.z); v.w = tf32_rna(v.w);
        d[lane + 32 * i] = v;
    }
}

// weight pre-round to tf32 (removes mma.sync truncation bias)
__global__ void cvt_kernel(const float* __restrict__ src, float* __restrict__ dst) {
    const size_t i = (size_t)blockIdx.x * blockDim.x + threadIdx.x;
    float4 v = reinterpret_cast<const float4*>(src)[i];
    v.x = tf32_rna(v.x); v.y = tf32_rna(v.y);
    v.z = tf32_rna(v.z); v.w = tf32_rna(v.w);
    reinterpret_cast<float4*>(dst)[i] = v;
}

// causal cumulative mean along L, output tf32-rounded (A of GEMM2)
__global__ void cummean_kernel(const float* __restrict__ V, float* __restrict__ avg) {
    const int gidx = blockIdx.x * blockDim.x + threadIdx.x;   // 0..2047
    const int b = gidx >> 10;
    const int d = gidx & 1023;
    const float* vp = V   + (size_t)b * LL * DIMS + d;
    float*       ap = avg + (size_t)b * LL * DIMS + d;
    float acc = 0.0f;
#pragma unroll 4
    for (int lq = 0; lq < LL; lq++) {
        acc += vp[(size_t)lq * DIMS];
        ap[(size_t)lq * DIMS] = tf32_rna(acc / (float)(lq + 1));
    }
}

// ---------------------------------------------------------------------------
// Launch
// ---------------------------------------------------------------------------
extern "C" void kernel_launch(void* const* d_in, const int* in_sizes, int n_in,
                              void* d_out, int out_size) {
    const void*  seq = d_in[0];
    const float* emb = (const float*)d_in[1];
    const float* WV  = (const float*)d_in[2];
    const float* WO  = (const float*)d_in[3];
    const float* bo  = (const float*)d_in[4];
    float* out = (float*)d_out;

    cudaFuncSetAttribute(gemm_tf32_mma,
                         cudaFuncAttributeMaxDynamicSharedMemorySize, SMEM_TOTAL);

    float *ge, *gv, *ga, *gwv, *gwo;
    cudaGetSymbolAddress((void**)&ge,  g_e);
    cudaGetSymbolAddress((void**)&gv,  g_V);
    cudaGetSymbolAddress((void**)&ga,  g_avg);
    cudaGetSymbolAddress((void**)&gwv, g_wv);
    cudaGetSymbolAddress((void**)&gwo, g_wo);

    detect_kernel<<<1, 256>>>(seq);
    gather_kernel<<<MROWS / 8, 256>>>(seq, emb, ge);
    cvt_kernel<<<(DIMS * DIMS) / 4 / 256, 256>>>(WV, gwv);
    cvt_kernel<<<(VOCAB * DIMS) / 4 / 256, 256>>>(WO, gwo);

    // GEMM1: V = e @ W_V^T   [4096 x 1024 x 1024]
    gemm_tf32_mma<<<dim3(DIMS / NT, MROWS / MT), 256, SMEM_TOTAL>>>(
        ge, gwv, nullptr, gv, MROWS, DIMS, DIMS);

    cummean_kernel<<<8, 256>>>(gv, ga);

    // GEMM2: out = avg @ W_out^T + b   [4096 x 32000 x 1024]
    gemm_tf32_mma<<<dim3(VOCAB / NT, MROWS / MT), 256, SMEM_TOTAL>>>(
        ga, gwo, bo, out, MROWS, VOCAB, DIMS);
}

// round 5
// speedup vs baseline: 1.2465x; 1.2465x over previous
#include <cuda_runtime.h>
#include <cuda_bf16.h>
#include <cstdint>

// ---------------------------------------------------------------------------
// Problem constants
// ---------------------------------------------------------------------------
static constexpr int VOCAB = 32000;
static constexpr int DIMS  = 1024;
static constexpr int BB    = 2;
static constexpr int LL    = 2048;
static constexpr int MROWS = BB * LL;          // 4096
static constexpr int SEGS  = 32;               // cummean scan segments
static constexpr int SEGL  = LL / SEGS;        // 64

// Scratch (static device globals: allocation-free)
__device__ float g_e  [MROWS * DIMS];          // tf32-rounded embeddings (A of GEMM1)
__device__ float g_V  [MROWS * DIMS];          // GEMM1 output (fp32)
__device__ float g_avg[MROWS * DIMS];          // tf32-rounded cummean (A of GEMM2)
__device__ float g_wv [DIMS * DIMS];           // tf32-rounded W_V
__device__ float g_wo [VOCAB * DIMS];          // tf32-rounded W_out
__device__ float g_seg[BB * SEGS * DIMS];      // segment sums for scan
__device__ int   g_is64;

// ---------------------------------------------------------------------------
// PTX helpers (base sm_100-compatible: cp.async + ldmatrix + mma.sync)
// ---------------------------------------------------------------------------
__device__ __forceinline__ uint32_t smem_u32(const void* p) {
    uint32_t a;
    asm("{ .reg .u64 t; cvta.to.shared.u64 t, %1; cvt.u32.u64 %0, t; }" : "=r"(a) : "l"(p));
    return a;
}

#define CP_ASYNC16(dst, src) \
    asm volatile("cp.async.cg.shared.global [%0], [%1], 16;" :: "r"(dst), "l"(src) : "memory")
#define CP_COMMIT() asm volatile("cp.async.commit_group;" ::: "memory")
#define CP_WAIT1()  asm volatile("cp.async.wait_group 1;" ::: "memory")

__device__ __forceinline__ void ldsm_x4(uint32_t* r, uint32_t addr) {
    asm volatile("ldmatrix.sync.aligned.m8n8.x4.shared.b16 {%0,%1,%2,%3}, [%4];"
                 : "=r"(r[0]), "=r"(r[1]), "=r"(r[2]), "=r"(r[3]) : "r"(addr));
}

__device__ __forceinline__ void mma_tf32(float* c, const uint32_t* a,
                                         uint32_t b0, uint32_t b1) {
    asm volatile(
        "mma.sync.aligned.m16n8k8.row.col.f32.tf32.tf32.f32 "
        "{%0,%1,%2,%3}, {%4,%5,%6,%7}, {%8,%9}, {%0,%1,%2,%3};"
        : "+f"(c[0]), "+f"(c[1]), "+f"(c[2]), "+f"(c[3])
        : "r"(a[0]), "r"(a[1]), "r"(a[2]), "r"(a[3]), "r"(b0), "r"(b1));
}

// cvt.rna.tf32.f32: destination must be a .b32 register
__device__ __forceinline__ float tf32_rna(float x) {
    uint32_t r;
    asm("cvt.rna.tf32.f32 %0, %1;" : "=r"(r) : "f"(x));
    return __uint_as_float(r);
}

// ---------------------------------------------------------------------------
// GEMM: C[M,N] = A[M,K] * B[N,K]^T (+bias), tf32 mma.sync, fp32 accumulate.
// CTA tile 128(M) x 256(N) x 32(K); 8 warps (2x4) of 64x64; 3-stage cp.async.
// Fragment double-buffering across ks steps; ONE __syncthreads per K-iter.
// ---------------------------------------------------------------------------
static constexpr int MT = 128;
static constexpr int NT = 256;
static constexpr int KC = 32;                      // floats of K per chunk (128B/row)
static constexpr int STAGES = 3;
static constexpr int ROWB = 144;                   // padded row stride in bytes
static constexpr int A_BYTES = MT * ROWB;          // 18432
static constexpr int B_BYTES = NT * ROWB;          // 36864
static constexpr int BUF     = A_BYTES + B_BYTES;  // 55296
static constexpr int SMEM_TOTAL = STAGES * BUF;    // 165888

__device__ __forceinline__ void load_chunk(uint32_t bufb,
                                           const float* __restrict__ A,
                                           const float* __restrict__ Bm,
                                           int mbase, int nbase, int K, int kc, int tid) {
    const int kofs = kc * KC;
#pragma unroll
    for (int i = 0; i < 4; i++) {
        int j = tid + (i << 8);
        int r = j >> 3, s = j & 7;
        const float* src = A + (size_t)(mbase + r) * K + kofs + s * 4;
        CP_ASYNC16(bufb + (uint32_t)(r * ROWB + s * 16), src);
    }
#pragma unroll
    for (int i = 0; i < 8; i++) {
        int j = tid + (i << 8);
        int r = j >> 3, s = j & 7;
        const float* src = Bm + (size_t)(nbase + r) * K + kofs + s * 4;
        CP_ASYNC16(bufb + (uint32_t)A_BYTES + (uint32_t)(r * ROWB + s * 16), src);
    }
}

__device__ __forceinline__ void load_frags(uint32_t bufb, uint32_t a_lane, uint32_t b_lane,
                                           int ks, uint32_t a[4][4], uint32_t b[4][4]) {
    const uint32_t boff = (uint32_t)(ks * 32);
#pragma unroll
    for (int mt = 0; mt < 4; mt++)
        ldsm_x4(a[mt], bufb + a_lane + (uint32_t)(mt * 16 * ROWB) + boff);
#pragma unroll
    for (int np = 0; np < 4; np++)
        ldsm_x4(b[np], bufb + b_lane + (uint32_t)(np * 16 * ROWB) + boff);
}

__global__ void __launch_bounds__(256, 1)
gemm_tf32_mma(const float* __restrict__ A, const float* __restrict__ Bm,
              const float* __restrict__ bias, float* __restrict__ C,
              int M, int N, int K) {
    extern __shared__ __align__(16) char smem[];
    const uint32_t sb = smem_u32(smem);
    const int tid = threadIdx.x;
    const int wid = tid >> 5;
    const int l   = tid & 31;
    const int wm  = wid >> 2;          // 0..1  (M warp row, 64 rows each)
    const int wn  = wid & 3;           // 0..3  (N warp col, 64 cols each)
    const int mbase = blockIdx.y * MT;
    const int nbase = blockIdx.x * NT;

    const int     lrow = (l & 7) + ((l >> 3) & 1) * 8;
    const uint32_t lhi = (uint32_t)((l >> 4) * 16);
    const uint32_t a_lane = (uint32_t)((wm * 64 + lrow) * ROWB) + lhi;
    const uint32_t b_lane = (uint32_t)A_BYTES + (uint32_t)((wn * 64 + lrow) * ROWB) + lhi;

    float c[4][8][4];
#pragma unroll
    for (int mt = 0; mt < 4; mt++)
#pragma unroll
        for (int nt = 0; nt < 8; nt++)
#pragma unroll
            for (int q = 0; q < 4; q++) c[mt][nt][q] = 0.0f;

    const int nch = K / KC;

    // prologue: prefetch 2 chunks
    load_chunk(sb, A, Bm, mbase, nbase, K, 0, tid);
    CP_COMMIT();
    load_chunk(sb + BUF, A, Bm, mbase, nbase, K, 1, tid);
    CP_COMMIT();

    uint32_t afr[2][4][4], bfr[2][4][4];
    uint32_t slot = 0;
    for (int kc = 0; kc < nch; kc++) {
        CP_WAIT1();                    // chunk kc resident
        __syncthreads();               // all warps done with slot (kc-1)%3 reads
        const uint32_t bufb = sb + slot * BUF;
        if (kc + 2 < nch) {            // refill the slot everyone just released
            uint32_t ws = slot + 2; if (ws >= STAGES) ws -= STAGES;
            load_chunk(sb + ws * BUF, A, Bm, mbase, nbase, K, kc + 2, tid);
        }
        CP_COMMIT();                   // one group per iter keeps wait count aligned

        load_frags(bufb, a_lane, b_lane, 0, afr[0], bfr[0]);
#pragma unroll
        for (int ks = 0; ks < 4; ks++) {
            const int cur = ks & 1;
            if (ks < 3)                // prefetch next fragments behind the MMAs
                load_frags(bufb, a_lane, b_lane, ks + 1, afr[cur ^ 1], bfr[cur ^ 1]);
#pragma unroll
            for (int mt = 0; mt < 4; mt++)
#pragma unroll
                for (int nt = 0; nt < 8; nt++) {
                    const int np = nt >> 1, od = nt & 1;
                    mma_tf32(c[mt][nt], afr[cur][mt], bfr[cur][np][od], bfr[cur][np][2 + od]);
                }
        }
        slot++; if (slot >= STAGES) slot = 0;
        // no trailing barrier: next iter's top barrier protects slot reuse
    }

    // Epilogue
    const int g = l >> 2, t = l & 3;
    const int row0 = mbase + wm * 64 + g;
    const int colb = nbase + wn * 64 + t * 2;
#pragma unroll
    for (int nt = 0; nt < 8; nt++) {
        float2 bv = make_float2(0.0f, 0.0f);
        if (bias) bv = *reinterpret_cast<const float2*>(bias + colb + nt * 8);
#pragma unroll
        for (int mt = 0; mt < 4; mt++) {
            const int r = row0 + mt * 16;
            float2 v0 = make_float2(c[mt][nt][0] + bv.x, c[mt][nt][1] + bv.y);
            float2 v1 = make_float2(c[mt][nt][2] + bv.x, c[mt][nt][3] + bv.y);
            *reinterpret_cast<float2*>(C + (size_t)r * N + colb + nt * 8)       = v0;
            *reinterpret_cast<float2*>(C + (size_t)(r + 8) * N + colb + nt * 8) = v1;
        }
    }
}

// ---------------------------------------------------------------------------
// Small kernels
// ---------------------------------------------------------------------------
__global__ void detect_kernel(const void* seq) {
    __shared__ int ok;
    if (threadIdx.x == 0) ok = 1;
    __syncthreads();
    const long long* p = (const long long*)seq;   // reads 16KB <= int32 buffer size
    for (int i = threadIdx.x; i < MROWS / 2; i += blockDim.x) {
        long long v = p[i];
        if (v < 0 || v >= VOCAB) ok = 0;
    }
    __syncthreads();
    if (threadIdx.x == 0) g_is64 = ok;
}

__global__ void gather_kernel(const void* seq, const float* __restrict__ emb,
                              float* __restrict__ e) {
    const int row  = blockIdx.x * 8 + (threadIdx.x >> 5);
    const int lane = threadIdx.x & 31;
    long long tok;
    if (g_is64) tok = ((const long long*)seq)[row];
    else        tok = (long long)((const int*)seq)[row];
    const float4* s = (const float4*)(emb + (size_t)tok * DIMS);
    float4*       d = (float4*)(e + (size_t)row * DIMS);
#pragma unroll
    for (int i = 0; i < 8; i++) {
        float4 v = s[lane + 32 * i];
        v.x = tf32_rna(v.x); v.y = tf32_rna(v.y);
        v.z = tf32_rna(v.z); v.w = tf32_rna(v.w);
        d[lane + 32 * i] = v;
    }
}

__global__ void cvt_kernel(const float* __restrict__ src, float* __restrict__ dst) {
    const size_t i = (size_t)blockIdx.x * blockDim.x + threadIdx.x;
    float4 v = reinterpret_cast<const float4*>(src)[i];
    v.x = tf32_rna(v.x); v.y = tf32_rna(v.y);
    v.z = tf32_rna(v.z); v.w = tf32_rna(v.w);
    reinterpret_cast<float4*>(dst)[i] = v;
}

// --- parallel causal cumulative mean: 2-pass segmented scan ----------------
// pass 1: per-(b,seg,dim4) partial sums over 64 rows
__global__ void segsum_kernel(const float* __restrict__ V, float* __restrict__ S) {
    const int b   = blockIdx.x / SEGS;
    const int seg = blockIdx.x % SEGS;
    const int d   = threadIdx.x * 4;
    const float* vp = V + ((size_t)b * LL + (size_t)seg * SEGL) * DIMS + d;
    float4 acc = make_float4(0.f, 0.f, 0.f, 0.f);
#pragma unroll 8
    for (int lq = 0; lq < SEGL; lq++) {
        float4 v = *reinterpret_cast<const float4*>(vp + (size_t)lq * DIMS);
        acc.x += v.x; acc.y += v.y; acc.z += v.z; acc.w += v.w;
    }
    *reinterpret_cast<float4*>(S + ((size_t)b * SEGS + seg) * DIMS + d) = acc;
}

// pass 2: prefix of segment sums + in-segment running mean, tf32-rounded
__global__ void cummean_apply(const float* __restrict__ V, const float* __restrict__ S,
                              float* __restrict__ avg) {
    const int b   = blockIdx.x / SEGS;
    const int seg = blockIdx.x % SEGS;
    const int d   = threadIdx.x * 4;
    float4 acc = make_float4(0.f, 0.f, 0.f, 0.f);
    for (int j = 0; j < seg; j++) {
        float4 s = *reinterpret_cast<const float4*>(S + ((size_t)b * SEGS + j) * DIMS + d);
        acc.x += s.x; acc.y += s.y; acc.z += s.z; acc.w += s.w;
    }
    const float* vp = V   + ((size_t)b * LL + (size_t)seg * SEGL) * DIMS + d;
    float*       ap = avg + ((size_t)b * LL + (size_t)seg * SEGL) * DIMS + d;
#pragma unroll 4
    for (int lq = 0; lq < SEGL; lq++) {
        float4 v = *reinterpret_cast<const float4*>(vp + (size_t)lq * DIMS);
        acc.x += v.x; acc.y += v.y; acc.z += v.z; acc.w += v.w;
        const float inv = 1.0f / (float)(seg * SEGL + lq + 1);
        float4 o;
        o.x = tf32_rna(acc.x * inv); o.y = tf32_rna(acc.y * inv);
        o.z = tf32_rna(acc.z * inv); o.w = tf32_rna(acc.w * inv);
        *reinterpret_cast<float4*>(ap + (size_t)lq * DIMS) = o;
    }
}

// ---------------------------------------------------------------------------
// Launch
// ---------------------------------------------------------------------------
extern "C" void kernel_launch(void* const* d_in, const int* in_sizes, int n_in,
                              void* d_out, int out_size) {
    const void*  seq = d_in[0];
    const float* emb = (const float*)d_in[1];
    const float* WV  = (const float*)d_in[2];
    const float* WO  = (const float*)d_in[3];
    const float* bo  = (const float*)d_in[4];
    float* out = (float*)d_out;

    cudaFuncSetAttribute(gemm_tf32_mma,
                         cudaFuncAttributeMaxDynamicSharedMemorySize, SMEM_TOTAL);

    float *ge, *gv, *ga, *gwv, *gwo, *gs;
    cudaGetSymbolAddress((void**)&ge,  g_e);
    cudaGetSymbolAddress((void**)&gv,  g_V);
    cudaGetSymbolAddress((void**)&ga,  g_avg);
    cudaGetSymbolAddress((void**)&gwv, g_wv);
    cudaGetSymbolAddress((void**)&gwo, g_wo);
    cudaGetSymbolAddress((void**)&gs,  g_seg);

    detect_kernel<<<1, 256>>>(seq);
    gather_kernel<<<MROWS / 8, 256>>>(seq, emb, ge);
    cvt_kernel<<<(DIMS * DIMS) / 4 / 256, 256>>>(WV, gwv);
    cvt_kernel<<<(VOCAB * DIMS) / 4 / 256, 256>>>(WO, gwo);

    // GEMM1: V = e @ W_V^T   [4096 x 1024 x 1024]
    gemm_tf32_mma<<<dim3(DIMS / NT, MROWS / MT), 256, SMEM_TOTAL>>>(
        ge, gwv, nullptr, gv, MROWS, DIMS, DIMS);

    segsum_kernel<<<BB * SEGS, 256>>>(gv, gs);
    cummean_apply<<<BB * SEGS, 256>>>(gv, gs, ga);

    // GEMM2: out = avg @ W_out^T + b   [4096 x 32000 x 1024]
    gemm_tf32_mma<<<dim3(VOCAB / NT, MROWS / MT), 256, SMEM_TOTAL>>>(
        ga, gwo, bo, out, MROWS, VOCAB, DIMS);
}

// round 6
// speedup vs baseline: 2.3162x; 1.8582x over previous
#include <cuda_runtime.h>
#include <cuda_fp16.h>
#include <cstdint>

// ---------------------------------------------------------------------------
// Problem constants
// ---------------------------------------------------------------------------
static constexpr int VOCAB = 32000;
static constexpr int DIMS  = 1024;
static constexpr int BB    = 2;
static constexpr int LL    = 2048;
static constexpr int MROWS = BB * LL;          // 4096
static constexpr int SEGS  = 32;               // cummean scan segments
static constexpr int SEGL  = LL / SEGS;        // 64

// Scratch (static device globals: allocation-free)
__device__ __half g_e  [MROWS * DIMS];         // fp16 embeddings (A of GEMM1)
__device__ float  g_V  [MROWS * DIMS];         // GEMM1 output (fp32)
__device__ __half g_avg[MROWS * DIMS];         // fp16 cummean (A of GEMM2)
__device__ __half g_wv [DIMS * DIMS];          // fp16 W_V
__device__ __half g_wo [VOCAB * DIMS];         // fp16 W_out
__device__ float  g_seg[BB * SEGS * DIMS];     // segment sums for scan
__device__ int    g_is64;

// ---------------------------------------------------------------------------
// PTX helpers (base sm_100-compatible: cp.async + ldmatrix + mma.sync fp16)
// ---------------------------------------------------------------------------
__device__ __forceinline__ uint32_t smem_u32(const void* p) {
    uint32_t a;
    asm("{ .reg .u64 t; cvta.to.shared.u64 t, %1; cvt.u32.u64 %0, t; }" : "=r"(a) : "l"(p));
    return a;
}

#define CP_ASYNC16(dst, src) \
    asm volatile("cp.async.cg.shared.global [%0], [%1], 16;" :: "r"(dst), "l"(src) : "memory")
#define CP_COMMIT() asm volatile("cp.async.commit_group;" ::: "memory")
#define CP_WAIT1()  asm volatile("cp.async.wait_group 1;" ::: "memory")

__device__ __forceinline__ void ldsm_x4(uint32_t* r, uint32_t addr) {
    asm volatile("ldmatrix.sync.aligned.m8n8.x4.shared.b16 {%0,%1,%2,%3}, [%4];"
                 : "=r"(r[0]), "=r"(r[1]), "=r"(r[2]), "=r"(r[3]) : "r"(addr));
}

// fp16 MMA, fp32 accumulate: D[16,8] += A[16,16] * B[16,8] (B col-major = N,K row)
__device__ __forceinline__ void mma_f16(float* c, const uint32_t* a,
                                        uint32_t b0, uint32_t b1) {
    asm volatile(
        "mma.sync.aligned.m16n8k16.row.col.f32.f16.f16.f32 "
        "{%0,%1,%2,%3}, {%4,%5,%6,%7}, {%8,%9}, {%0,%1,%2,%3};"
        : "+f"(c[0]), "+f"(c[1]), "+f"(c[2]), "+f"(c[3])
        : "r"(a[0]), "r"(a[1]), "r"(a[2]), "r"(a[3]), "r"(b0), "r"(b1));
}

// ---------------------------------------------------------------------------
// GEMM: C[M,N] = A[M,K] * B[N,K]^T (+bias), fp16 mma.sync, fp32 accumulate.
// CTA tile 128(M) x 256(N) x 64(K); 8 warps (2x4) of 64x64; 3-stage cp.async.
// Rows are 64 halves (128B) padded to 144B: conflict-free stores + ldmatrix.
// ---------------------------------------------------------------------------
static constexpr int MT = 128;
static constexpr int NT = 256;
static constexpr int KC = 64;                      // halves of K per chunk (128B/row)
static constexpr int STAGES = 3;
static constexpr int ROWB = 144;                   // padded row stride in bytes
static constexpr int A_BYTES = MT * ROWB;          // 18432
static constexpr int B_BYTES = NT * ROWB;          // 36864
static constexpr int BUF     = A_BYTES + B_BYTES;  // 55296
static constexpr int SMEM_TOTAL = STAGES * BUF;    // 165888

__device__ __forceinline__ void load_chunk(uint32_t bufb,
                                           const __half* __restrict__ A,
                                           const __half* __restrict__ Bm,
                                           int mbase, int nbase, int K, int kc, int tid) {
    const int kofs = kc * KC;
#pragma unroll
    for (int i = 0; i < 4; i++) {
        int j = tid + (i << 8);
        int r = j >> 3, s = j & 7;
        const __half* src = A + (size_t)(mbase + r) * K + kofs + s * 8;
        CP_ASYNC16(bufb + (uint32_t)(r * ROWB + s * 16), src);
    }
#pragma unroll
    for (int i = 0; i < 8; i++) {
        int j = tid + (i << 8);
        int r = j >> 3, s = j & 7;
        const __half* src = Bm + (size_t)(nbase + r) * K + kofs + s * 8;
        CP_ASYNC16(bufb + (uint32_t)A_BYTES + (uint32_t)(r * ROWB + s * 16), src);
    }
}

// load fragments for one k16 step (4 A tiles m16k16, 4 B tiles n16k16)
__device__ __forceinline__ void load_frags(uint32_t bufb, uint32_t a_lane, uint32_t b_lane,
                                           int ks, uint32_t a[4][4], uint32_t b[4][4]) {
    const uint32_t boff = (uint32_t)(ks * 32);     // 16 halves = 32B per k16 step
#pragma unroll
    for (int mt = 0; mt < 4; mt++)
        ldsm_x4(a[mt], bufb + a_lane + (uint32_t)(mt * 16 * ROWB) + boff);
#pragma unroll
    for (int np = 0; np < 4; np++)
        ldsm_x4(b[np], bufb + b_lane + (uint32_t)(np * 16 * ROWB) + boff);
}

__global__ void __launch_bounds__(256, 1)
gemm_f16_mma(const __half* __restrict__ A, const __half* __restrict__ Bm,
             const float* __restrict__ bias, float* __restrict__ C,
             int M, int N, int K) {
    extern __shared__ __align__(16) char smem[];
    const uint32_t sb = smem_u32(smem);
    const int tid = threadIdx.x;
    const int wid = tid >> 5;
    const int l   = tid & 31;
    const int wm  = wid >> 2;          // 0..1  (M warp row, 64 rows each)
    const int wn  = wid & 3;           // 0..3  (N warp col, 64 cols each)
    const int mbase = blockIdx.y * MT;
    const int nbase = blockIdx.x * NT;

    // ldmatrix lane->address: lanes 0-7 rows 0-7, 8-15 rows 8-15 (k0-7),
    // lanes 16-23 rows 0-7, 24-31 rows 8-15 (k8-15, +16B)
    const int      lrow = (l & 7) + ((l >> 3) & 1) * 8;
    const uint32_t lhi  = (uint32_t)((l >> 4) * 16);
    const uint32_t a_lane = (uint32_t)((wm * 64 + lrow) * ROWB) + lhi;
    const uint32_t b_lane = (uint32_t)A_BYTES + (uint32_t)((wn * 64 + lrow) * ROWB) + lhi;

    float c[4][8][4];
#pragma unroll
    for (int mt = 0; mt < 4; mt++)
#pragma unroll
        for (int nt = 0; nt < 8; nt++)
#pragma unroll
            for (int q = 0; q < 4; q++) c[mt][nt][q] = 0.0f;

    const int nch = K / KC;            // 16 for K=1024

    load_chunk(sb, A, Bm, mbase, nbase, K, 0, tid);
    CP_COMMIT();
    load_chunk(sb + BUF, A, Bm, mbase, nbase, K, 1, tid);
    CP_COMMIT();

    uint32_t afr[2][4][4], bfr[2][4][4];
    uint32_t slot = 0;
    for (int kc = 0; kc < nch; kc++) {
        CP_WAIT1();
        __syncthreads();
        const uint32_t bufb = sb + slot * BUF;
        if (kc + 2 < nch) {
            uint32_t ws = slot + 2; if (ws >= STAGES) ws -= STAGES;
            load_chunk(sb + ws * BUF, A, Bm, mbase, nbase, K, kc + 2, tid);
        }
        CP_COMMIT();

        load_frags(bufb, a_lane, b_lane, 0, afr[0], bfr[0]);
#pragma unroll
        for (int ks = 0; ks < 4; ks++) {           // 4 x k16 = K chunk of 64
            const int cur = ks & 1;
            if (ks < 3)
                load_frags(bufb, a_lane, b_lane, ks + 1, afr[cur ^ 1], bfr[cur ^ 1]);
#pragma unroll
            for (int mt = 0; mt < 4; mt++)
#pragma unroll
                for (int nt = 0; nt < 8; nt++) {
                    const int np = nt >> 1, od = nt & 1;
                    mma_f16(c[mt][nt], afr[cur][mt], bfr[cur][np][od], bfr[cur][np][2 + od]);
                }
        }
        slot++; if (slot >= STAGES) slot = 0;
    }

    // Epilogue: rows = mbase+wm*64+mt*16+{g,g+8}, cols = nbase+wn*64+nt*8+2t+{0,1}
    const int g = l >> 2, t = l & 3;
    const int row0 = mbase + wm * 64 + g;
    const int colb = nbase + wn * 64 + t * 2;
#pragma unroll
    for (int nt = 0; nt < 8; nt++) {
        float2 bv = make_float2(0.0f, 0.0f);
        if (bias) bv = *reinterpret_cast<const float2*>(bias + colb + nt * 8);
#pragma unroll
        for (int mt = 0; mt < 4; mt++) {
            const int r = row0 + mt * 16;
            float2 v0 = make_float2(c[mt][nt][0] + bv.x, c[mt][nt][1] + bv.y);
            float2 v1 = make_float2(c[mt][nt][2] + bv.x, c[mt][nt][3] + bv.y);
            *reinterpret_cast<float2*>(C + (size_t)r * N + colb + nt * 8)       = v0;
            *reinterpret_cast<float2*>(C + (size_t)(r + 8) * N + colb + nt * 8) = v1;
        }
    }
}

// ---------------------------------------------------------------------------
// Small kernels
// ---------------------------------------------------------------------------
__global__ void detect_kernel(const void* seq) {
    __shared__ int ok;
    if (threadIdx.x == 0) ok = 1;
    __syncthreads();
    const long long* p = (const long long*)seq;   // reads 16KB <= int32 buffer size
    for (int i = threadIdx.x; i < MROWS / 2; i += blockDim.x) {
        long long v = p[i];
        if (v < 0 || v >= VOCAB) ok = 0;
    }
    __syncthreads();
    if (threadIdx.x == 0) g_is64 = ok;
}

// gather fp32 embeddings -> fp16 A of GEMM1
__global__ void gather_kernel(const void* seq, const float* __restrict__ emb,
                              __half* __restrict__ e) {
    const int row  = blockIdx.x * 8 + (threadIdx.x >> 5);
    const int lane = threadIdx.x & 31;
    long long tok;
    if (g_is64) tok = ((const long long*)seq)[row];
    else        tok = (long long)((const int*)seq)[row];
    const float4* s = (const float4*)(emb + (size_t)tok * DIMS);
    __half2*      d = (__half2*)(e + (size_t)row * DIMS);
#pragma unroll
    for (int i = 0; i < 8; i++) {
        float4 v = s[lane + 32 * i];
        d[(lane + 32 * i) * 2 + 0] = __floats2half2_rn(v.x, v.y);
        d[(lane + 32 * i) * 2 + 1] = __floats2half2_rn(v.z, v.w);
    }
}

// fp32 weights -> fp16 (round-to-nearest)
__global__ void cvt_kernel(const float* __restrict__ src, __half* __restrict__ dst) {
    const size_t i = (size_t)blockIdx.x * blockDim.x + threadIdx.x;
    float4 v = reinterpret_cast<const float4*>(src)[i];
    __half2 h0 = __floats2half2_rn(v.x, v.y);
    __half2 h1 = __floats2half2_rn(v.z, v.w);
    reinterpret_cast<__half2*>(dst)[i * 2 + 0] = h0;
    reinterpret_cast<__half2*>(dst)[i * 2 + 1] = h1;
}

// --- parallel causal cumulative mean: 2-pass segmented scan ----------------
__global__ void segsum_kernel(const float* __restrict__ V, float* __restrict__ S) {
    const int b   = blockIdx.x / SEGS;
    const int seg = blockIdx.x % SEGS;
    const int d   = threadIdx.x * 4;
    const float* vp = V + ((size_t)b * LL + (size_t)seg * SEGL) * DIMS + d;
    float4 acc = make_float4(0.f, 0.f, 0.f, 0.f);
#pragma unroll 8
    for (int lq = 0; lq < SEGL; lq++) {
        float4 v = *reinterpret_cast<const float4*>(vp + (size_t)lq * DIMS);
        acc.x += v.x; acc.y += v.y; acc.z += v.z; acc.w += v.w;
    }
    *reinterpret_cast<float4*>(S + ((size_t)b * SEGS + seg) * DIMS + d) = acc;
}

// prefix of segment sums + in-segment running mean -> fp16 A of GEMM2
__global__ void cummean_apply(const float* __restrict__ V, const float* __restrict__ S,
                              __half* __restrict__ avg) {
    const int b   = blockIdx.x / SEGS;
    const int seg = blockIdx.x % SEGS;
    const int d   = threadIdx.x * 4;
    float4 acc = make_float4(0.f, 0.f, 0.f, 0.f);
    for (int j = 0; j < seg; j++) {
        float4 s = *reinterpret_cast<const float4*>(S + ((size_t)b * SEGS + j) * DIMS + d);
        acc.x += s.x; acc.y += s.y; acc.z += s.z; acc.w += s.w;
    }
    const float* vp = V   + ((size_t)b * LL + (size_t)seg * SEGL) * DIMS + d;
    __half*      ap = avg + ((size_t)b * LL + (size_t)seg * SEGL) * DIMS + d;
#pragma unroll 4
    for (int lq = 0; lq < SEGL; lq++) {
        float4 v = *reinterpret_cast<const float4*>(vp + (size_t)lq * DIMS);
        acc.x += v.x; acc.y += v.y; acc.z += v.z; acc.w += v.w;
        const float inv = 1.0f / (float)(seg * SEGL + lq + 1);
        __half2 h0 = __floats2half2_rn(acc.x * inv, acc.y * inv);
        __half2 h1 = __floats2half2_rn(acc.z * inv, acc.w * inv);
        *reinterpret_cast<__half2*>(ap + (size_t)lq * DIMS + 0) = h0;
        *reinterpret_cast<__half2*>(ap + (size_t)lq * DIMS + 2) = h1;
    }
}

// ---------------------------------------------------------------------------
// Launch
// ---------------------------------------------------------------------------
extern "C" void kernel_launch(void* const* d_in, const int* in_sizes, int n_in,
                              void* d_out, int out_size) {
    const void*  seq = d_in[0];
    const float* emb = (const float*)d_in[1];
    const float* WV  = (const float*)d_in[2];
    const float* WO  = (const float*)d_in[3];
    const float* bo  = (const float*)d_in[4];
    float* out = (float*)d_out;

    cudaFuncSetAttribute(gemm_f16_mma,
                         cudaFuncAttributeMaxDynamicSharedMemorySize, SMEM_TOTAL);

    __half *ge, *ga, *gwv, *gwo;
    float *gv, *gs;
    cudaGetSymbolAddress((void**)&ge,  g_e);
    cudaGetSymbolAddress((void**)&gv,  g_V);
    cudaGetSymbolAddress((void**)&ga,  g_avg);
    cudaGetSymbolAddress((void**)&gwv, g_wv);
    cudaGetSymbolAddress((void**)&gwo, g_wo);
    cudaGetSymbolAddress((void**)&gs,  g_seg);

    detect_kernel<<<1, 256>>>(seq);
    gather_kernel<<<MROWS / 8, 256>>>(seq, emb, ge);
    cvt_kernel<<<(DIMS * DIMS) / 4 / 256, 256>>>(WV, gwv);
    cvt_kernel<<<(VOCAB * DIMS) / 4 / 256, 256>>>(WO, gwo);

    // GEMM1: V = e @ W_V^T   [4096 x 1024 x 1024]
    gemm_f16_mma<<<dim3(DIMS / NT, MROWS / MT), 256, SMEM_TOTAL>>>(
        ge, gwv, nullptr, gv, MROWS, DIMS, DIMS);

    segsum_kernel<<<BB * SEGS, 256>>>(gv, gs);
    cummean_apply<<<BB * SEGS, 256>>>(gv, gs, ga);

    // GEMM2: out = avg @ W_out^T + b   [4096 x 32000 x 1024]
    gemm_f16_mma<<<dim3(VOCAB / NT, MROWS / MT), 256, SMEM_TOTAL>>>(
        ga, gwo, bo, out, MROWS, VOCAB, DIMS);
}

// round 7
// speedup vs baseline: 2.5089x; 1.0832x over previous
#include <cuda_runtime.h>
#include <cuda_fp16.h>
#include <cstdint>

// ---------------------------------------------------------------------------
// Problem constants
// ---------------------------------------------------------------------------
static constexpr int VOCAB = 32000;
static constexpr int DIMS  = 1024;
static constexpr int BB    = 2;
static constexpr int LL    = 2048;
static constexpr int MROWS = BB * LL;          // 4096
static constexpr int SEGS  = 32;               // cummean scan segments
static constexpr int SEGL  = LL / SEGS;        // 64

// Scratch (static device globals: allocation-free)
__device__ __half g_e  [MROWS * DIMS];         // fp16 embeddings (A of GEMM1)
__device__ float  g_V  [MROWS * DIMS];         // GEMM1 output (fp32)
__device__ __half g_avg[MROWS * DIMS];         // fp16 cummean (A of GEMM2)
__device__ __half g_wv [DIMS * DIMS];          // fp16 W_V
__device__ __half g_wo [VOCAB * DIMS];         // fp16 W_out
__device__ float  g_seg[BB * SEGS * DIMS];     // segment sums for scan
__device__ int    g_is64;

// ---------------------------------------------------------------------------
// PTX helpers (base sm_100-compatible: cp.async + ldmatrix + mma.sync fp16)
// ---------------------------------------------------------------------------
__device__ __forceinline__ uint32_t smem_u32(const void* p) {
    uint32_t a;
    asm("{ .reg .u64 t; cvta.to.shared.u64 t, %1; cvt.u32.u64 %0, t; }" : "=r"(a) : "l"(p));
    return a;
}

#define CP_ASYNC16(dst, src) \
    asm volatile("cp.async.cg.shared.global [%0], [%1], 16;" :: "r"(dst), "l"(src) : "memory")
#define CP_COMMIT() asm volatile("cp.async.commit_group;" ::: "memory")
#define CP_WAIT1()  asm volatile("cp.async.wait_group 1;" ::: "memory")

__device__ __forceinline__ void ldsm_x4(uint32_t* r, uint32_t addr) {
    asm volatile("ldmatrix.sync.aligned.m8n8.x4.shared.b16 {%0,%1,%2,%3}, [%4];"
                 : "=r"(r[0]), "=r"(r[1]), "=r"(r[2]), "=r"(r[3]) : "r"(addr));
}

// fp16 MMA, fp32 accumulate: D[16,8] += A[16,16] * B[16,8] (B col-major = N,K row)
__device__ __forceinline__ void mma_f16(float* c, const uint32_t* a,
                                        uint32_t b0, uint32_t b1) {
    asm volatile(
        "mma.sync.aligned.m16n8k16.row.col.f32.f16.f16.f32 "
        "{%0,%1,%2,%3}, {%4,%5,%6,%7}, {%8,%9}, {%0,%1,%2,%3};"
        : "+f"(c[0]), "+f"(c[1]), "+f"(c[2]), "+f"(c[3])
        : "r"(a[0]), "r"(a[1]), "r"(a[2]), "r"(a[3]), "r"(b0), "r"(b1));
}

// ---------------------------------------------------------------------------
// GEMM: C[M,N] = A[M,K] * B[N,K]^T (+bias), fp16 mma.sync, fp32 accumulate.
// CTA tile 128(M) x 128(N) x 64(K); 4 warps (2x2) of 64x64; 3-stage cp.async.
// TWO CTAs per SM: when one CTA stalls at its chunk barrier, the other keeps
// the tensor pipe busy (tests the scheduling-gap vs HW-ceiling hypothesis).
// Rows are 64 halves (128B) padded to 144B: conflict-free stores + ldmatrix.
// ---------------------------------------------------------------------------
static constexpr int MT = 128;
static constexpr int NT = 128;
static constexpr int KC = 64;                      // halves of K per chunk (128B/row)
static constexpr int STAGES = 3;
static constexpr int THREADS = 128;
static constexpr int ROWB = 144;                   // padded row stride in bytes
static constexpr int A_BYTES = MT * ROWB;          // 18432
static constexpr int B_BYTES = NT * ROWB;          // 18432
static constexpr int BUF     = A_BYTES + B_BYTES;  // 36864
static constexpr int SMEM_TOTAL = STAGES * BUF;    // 110592 (x2 CTAs = 221184 < 227KB)

__device__ __forceinline__ void load_chunk(uint32_t bufb,
                                           const __half* __restrict__ A,
                                           const __half* __restrict__ Bm,
                                           int mbase, int nbase, int K, int kc, int tid) {
    const int kofs = kc * KC;
#pragma unroll
    for (int i = 0; i < 8; i++) {                  // A: 128 rows x 8 segs / 128 thr
        int j = tid + (i << 7);
        int r = j >> 3, s = j & 7;
        const __half* src = A + (size_t)(mbase + r) * K + kofs + s * 8;
        CP_ASYNC16(bufb + (uint32_t)(r * ROWB + s * 16), src);
    }
#pragma unroll
    for (int i = 0; i < 8; i++) {                  // B: 128 rows x 8 segs / 128 thr
        int j = tid + (i << 7);
        int r = j >> 3, s = j & 7;
        const __half* src = Bm + (size_t)(nbase + r) * K + kofs + s * 8;
        CP_ASYNC16(bufb + (uint32_t)A_BYTES + (uint32_t)(r * ROWB + s * 16), src);
    }
}

// load fragments for one k16 step (4 A tiles m16k16, 4 B tiles n16k16)
__device__ __forceinline__ void load_frags(uint32_t bufb, uint32_t a_lane, uint32_t b_lane,
                                           int ks, uint32_t a[4][4], uint32_t b[4][4]) {
    const uint32_t boff = (uint32_t)(ks * 32);     // 16 halves = 32B per k16 step
#pragma unroll
    for (int mt = 0; mt < 4; mt++)
        ldsm_x4(a[mt], bufb + a_lane + (uint32_t)(mt * 16 * ROWB) + boff);
#pragma unroll
    for (int np = 0; np < 4; np++)
        ldsm_x4(b[np], bufb + b_lane + (uint32_t)(np * 16 * ROWB) + boff);
}

__global__ void __launch_bounds__(THREADS, 2)
gemm_f16_mma(const __half* __restrict__ A, const __half* __restrict__ Bm,
             const float* __restrict__ bias, float* __restrict__ C,
             int M, int N, int K) {
    extern __shared__ __align__(16) char smem[];
    const uint32_t sb = smem_u32(smem);
    const int tid = threadIdx.x;
    const int wid = tid >> 5;
    const int l   = tid & 31;
    const int wm  = wid >> 1;          // 0..1  (M warp row, 64 rows each)
    const int wn  = wid & 1;           // 0..1  (N warp col, 64 cols each)
    const int mbase = blockIdx.y * MT;
    const int nbase = blockIdx.x * NT;

    // ldmatrix lane->address: lanes 0-15 rows 0-15 (k0-7), 16-31 same rows (k8-15)
    const int      lrow = (l & 7) + ((l >> 3) & 1) * 8;
    const uint32_t lhi  = (uint32_t)((l >> 4) * 16);
    const uint32_t a_lane = (uint32_t)((wm * 64 + lrow) * ROWB) + lhi;
    const uint32_t b_lane = (uint32_t)A_BYTES + (uint32_t)((wn * 64 + lrow) * ROWB) + lhi;

    float c[4][8][4];
#pragma unroll
    for (int mt = 0; mt < 4; mt++)
#pragma unroll
        for (int nt = 0; nt < 8; nt++)
#pragma unroll
            for (int q = 0; q < 4; q++) c[mt][nt][q] = 0.0f;

    const int nch = K / KC;            // 16 for K=1024

    load_chunk(sb, A, Bm, mbase, nbase, K, 0, tid);
    CP_COMMIT();
    load_chunk(sb + BUF, A, Bm, mbase, nbase, K, 1, tid);
    CP_COMMIT();

    uint32_t afr[2][4][4], bfr[2][4][4];
    uint32_t slot = 0;
    for (int kc = 0; kc < nch; kc++) {
        CP_WAIT1();
        __syncthreads();
        const uint32_t bufb = sb + slot * BUF;
        if (kc + 2 < nch) {
            uint32_t ws = slot + 2; if (ws >= STAGES) ws -= STAGES;
            load_chunk(sb + ws * BUF, A, Bm, mbase, nbase, K, kc + 2, tid);
        }
        CP_COMMIT();

        load_frags(bufb, a_lane, b_lane, 0, afr[0], bfr[0]);
#pragma unroll
        for (int ks = 0; ks < 4; ks++) {           // 4 x k16 = K chunk of 64
            const int cur = ks & 1;
            if (ks < 3)
                load_frags(bufb, a_lane, b_lane, ks + 1, afr[cur ^ 1], bfr[cur ^ 1]);
#pragma unroll
            for (int mt = 0; mt < 4; mt++)
#pragma unroll
                for (int nt = 0; nt < 8; nt++) {
                    const int np = nt >> 1, od = nt & 1;
                    mma_f16(c[mt][nt], afr[cur][mt], bfr[cur][np][od], bfr[cur][np][2 + od]);
                }
        }
        slot++; if (slot >= STAGES) slot = 0;
    }

    // Epilogue: rows = mbase+wm*64+mt*16+{g,g+8}, cols = nbase+wn*64+nt*8+2t+{0,1}
    const int g = l >> 2, t = l & 3;
    const int row0 = mbase + wm * 64 + g;
    const int colb = nbase + wn * 64 + t * 2;
#pragma unroll
    for (int nt = 0; nt < 8; nt++) {
        float2 bv = make_float2(0.0f, 0.0f);
        if (bias) bv = *reinterpret_cast<const float2*>(bias + colb + nt * 8);
#pragma unroll
        for (int mt = 0; mt < 4; mt++) {
            const int r = row0 + mt * 16;
            float2 v0 = make_float2(c[mt][nt][0] + bv.x, c[mt][nt][1] + bv.y);
            float2 v1 = make_float2(c[mt][nt][2] + bv.x, c[mt][nt][3] + bv.y);
            *reinterpret_cast<float2*>(C + (size_t)r * N + colb + nt * 8)       = v0;
            *reinterpret_cast<float2*>(C + (size_t)(r + 8) * N + colb + nt * 8) = v1;
        }
    }
}

// ---------------------------------------------------------------------------
// Small kernels
// ---------------------------------------------------------------------------
__global__ void detect_kernel(const void* seq) {
    __shared__ int ok;
    if (threadIdx.x == 0) ok = 1;
    __syncthreads();
    const long long* p = (const long long*)seq;   // reads 16KB <= int32 buffer size
    for (int i = threadIdx.x; i < MROWS / 2; i += blockDim.x) {
        long long v = p[i];
        if (v < 0 || v >= VOCAB) ok = 0;
    }
    __syncthreads();
    if (threadIdx.x == 0) g_is64 = ok;
}

// gather fp32 embeddings -> fp16 A of GEMM1
__global__ void gather_kernel(const void* seq, const float* __restrict__ emb,
                              __half* __restrict__ e) {
    const int row  = blockIdx.x * 8 + (threadIdx.x >> 5);
    const int lane = threadIdx.x & 31;
    long long tok;
    if (g_is64) tok = ((const long long*)seq)[row];
    else        tok = (long long)((const int*)seq)[row];
    const float4* s = (const float4*)(emb + (size_t)tok * DIMS);
    __half2*      d = (__half2*)(e + (size_t)row * DIMS);
#pragma unroll
    for (int i = 0; i < 8; i++) {
        float4 v = s[lane + 32 * i];
        d[(lane + 32 * i) * 2 + 0] = __floats2half2_rn(v.x, v.y);
        d[(lane + 32 * i) * 2 + 1] = __floats2half2_rn(v.z, v.w);
    }
}

// fp32 weights -> fp16 (round-to-nearest)
__global__ void cvt_kernel(const float* __restrict__ src, __half* __restrict__ dst) {
    const size_t i = (size_t)blockIdx.x * blockDim.x + threadIdx.x;
    float4 v = reinterpret_cast<const float4*>(src)[i];
    __half2 h0 = __floats2half2_rn(v.x, v.y);
    __half2 h1 = __floats2half2_rn(v.z, v.w);
    reinterpret_cast<__half2*>(dst)[i * 2 + 0] = h0;
    reinterpret_cast<__half2*>(dst)[i * 2 + 1] = h1;
}

// --- parallel causal cumulative mean: 2-pass segmented scan ----------------
__global__ void segsum_kernel(const float* __restrict__ V, float* __restrict__ S) {
    const int b   = blockIdx.x / SEGS;
    const int seg = blockIdx.x % SEGS;
    const int d   = threadIdx.x * 4;
    const float* vp = V + ((size_t)b * LL + (size_t)seg * SEGL) * DIMS + d;
    float4 acc = make_float4(0.f, 0.f, 0.f, 0.f);
#pragma unroll 8
    for (int lq = 0; lq < SEGL; lq++) {
        float4 v = *reinterpret_cast<const float4*>(vp + (size_t)lq * DIMS);
        acc.x += v.x; acc.y += v.y; acc.z += v.z; acc.w += v.w;
    }
    *reinterpret_cast<float4*>(S + ((size_t)b * SEGS + seg) * DIMS + d) = acc;
}

// prefix of segment sums + in-segment running mean -> fp16 A of GEMM2
__global__ void cummean_apply(const float* __restrict__ V, const float* __restrict__ S,
                              __half* __restrict__ avg) {
    const int b   = blockIdx.x / SEGS;
    const int seg = blockIdx.x % SEGS;
    const int d   = threadIdx.x * 4;
    float4 acc = make_float4(0.f, 0.f, 0.f, 0.f);
    for (int j = 0; j < seg; j++) {
        float4 s = *reinterpret_cast<const float4*>(S + ((size_t)b * SEGS + j) * DIMS + d);
        acc.x += s.x; acc.y += s.y; acc.z += s.z; acc.w += s.w;
    }
    const float* vp = V   + ((size_t)b * LL + (size_t)seg * SEGL) * DIMS + d;
    __half*      ap = avg + ((size_t)b * LL + (size_t)seg * SEGL) * DIMS + d;
#pragma unroll 4
    for (int lq = 0; lq < SEGL; lq++) {
        float4 v = *reinterpret_cast<const float4*>(vp + (size_t)lq * DIMS);
        acc.x += v.x; acc.y += v.y; acc.z += v.z; acc.w += v.w;
        const float inv = 1.0f / (float)(seg * SEGL + lq + 1);
        __half2 h0 = __floats2half2_rn(acc.x * inv, acc.y * inv);
        __half2 h1 = __floats2half2_rn(acc.z * inv, acc.w * inv);
        *reinterpret_cast<__half2*>(ap + (size_t)lq * DIMS + 0) = h0;
        *reinterpret_cast<__half2*>(ap + (size_t)lq * DIMS + 2) = h1;
    }
}

// ---------------------------------------------------------------------------
// Launch
// ---------------------------------------------------------------------------
extern "C" void kernel_launch(void* const* d_in, const int* in_sizes, int n_in,
                              void* d_out, int out_size) {
    const void*  seq = d_in[0];
    const float* emb = (const float*)d_in[1];
    const float* WV  = (const float*)d_in[2];
    const float* WO  = (const float*)d_in[3];
    const float* bo  = (const float*)d_in[4];
    float* out = (float*)d_out;

    cudaFuncSetAttribute(gemm_f16_mma,
                         cudaFuncAttributeMaxDynamicSharedMemorySize, SMEM_TOTAL);

    __half *ge, *ga, *gwv, *gwo;
    float *gv, *gs;
    cudaGetSymbolAddress((void**)&ge,  g_e);
    cudaGetSymbolAddress((void**)&gv,  g_V);
    cudaGetSymbolAddress((void**)&ga,  g_avg);
    cudaGetSymbolAddress((void**)&gwv, g_wv);
    cudaGetSymbolAddress((void**)&gwo, g_wo);
    cudaGetSymbolAddress((void**)&gs,  g_seg);

    detect_kernel<<<1, 256>>>(seq);
    gather_kernel<<<MROWS / 8, 256>>>(seq, emb, ge);
    cvt_kernel<<<(DIMS * DIMS) / 4 / 256, 256>>>(WV, gwv);
    cvt_kernel<<<(VOCAB * DIMS) / 4 / 256, 256>>>(WO, gwo);

    // GEMM1: V = e @ W_V^T   [4096 x 1024 x 1024]
    gemm_f16_mma<<<dim3(DIMS / NT, MROWS / MT), THREADS, SMEM_TOTAL>>>(
        ge, gwv, nullptr, gv, MROWS, DIMS, DIMS);

    segsum_kernel<<<BB * SEGS, 256>>>(gv, gs);
    cummean_apply<<<BB * SEGS, 256>>>(gv, gs, ga);

    // GEMM2: out = avg @ W_out^T + b   [4096 x 32000 x 1024]
    gemm_f16_mma<<<dim3(VOCAB / NT, MROWS / MT), THREADS, SMEM_TOTAL>>>(
        ga, gwo, bo, out, MROWS, VOCAB, DIMS);
}

// round 8
// speedup vs baseline: 2.5204x; 1.0046x over previous
#include <cuda_runtime.h>
#include <cuda_fp16.h>
#include <cstdint>

// ---------------------------------------------------------------------------
// Problem constants
// ---------------------------------------------------------------------------
static constexpr int VOCAB = 32000;
static constexpr int DIMS  = 1024;
static constexpr int BB    = 2;
static constexpr int LL    = 2048;
static constexpr int MROWS = BB * LL;          // 4096
static constexpr int SEGS  = 32;               // cummean scan segments
static constexpr int SEGL  = LL / SEGS;        // 64

// Scratch (static device globals: allocation-free)
__device__ __half g_e  [MROWS * DIMS];         // fp16 embeddings (A of GEMM1)
__device__ float  g_V  [MROWS * DIMS];         // GEMM1 output (fp32)
__device__ __half g_avg[MROWS * DIMS];         // fp16 cummean (A of GEMM2)
__device__ __half g_wv [DIMS * DIMS];          // fp16 W_V
__device__ __half g_wo [VOCAB * DIMS];         // fp16 W_out
__device__ float  g_seg[BB * SEGS * DIMS];     // segment sums for scan
__device__ int    g_is64;

// ---------------------------------------------------------------------------
// PTX helpers (base sm_100-compatible: cp.async + ldmatrix + mma.sync fp16)
// ---------------------------------------------------------------------------
__device__ __forceinline__ uint32_t smem_u32(const void* p) {
    uint32_t a;
    asm("{ .reg .u64 t; cvta.to.shared.u64 t, %1; cvt.u32.u64 %0, t; }" : "=r"(a) : "l"(p));
    return a;
}

#define CP_ASYNC16(dst, src) \
    asm volatile("cp.async.cg.shared.global [%0], [%1], 16;" :: "r"(dst), "l"(src) : "memory")
#define CP_COMMIT() asm volatile("cp.async.commit_group;" ::: "memory")
#define CP_WAIT1()  asm volatile("cp.async.wait_group 1;" ::: "memory")

__device__ __forceinline__ void ldsm_x4(uint32_t* r, uint32_t addr) {
    asm volatile("ldmatrix.sync.aligned.m8n8.x4.shared.b16 {%0,%1,%2,%3}, [%4];"
                 : "=r"(r[0]), "=r"(r[1]), "=r"(r[2]), "=r"(r[3]) : "r"(addr));
}

// fp16 MMA, fp32 accumulate: D[16,8] += A[16,16] * B[16,8] (B col-major = N,K row)
__device__ __forceinline__ void mma_f16(float* c, const uint32_t* a,
                                        uint32_t b0, uint32_t b1) {
    asm volatile(
        "mma.sync.aligned.m16n8k16.row.col.f32.f16.f16.f32 "
        "{%0,%1,%2,%3}, {%4,%5,%6,%7}, {%8,%9}, {%0,%1,%2,%3};"
        : "+f"(c[0]), "+f"(c[1]), "+f"(c[2]), "+f"(c[3])
        : "r"(a[0]), "r"(a[1]), "r"(a[2]), "r"(a[3]), "r"(b0), "r"(b1));
}

// ---------------------------------------------------------------------------
// GEMM: C[M,N] = A[M,K] * B[N,K]^T (+bias), fp16 mma.sync, fp32 accumulate.
// CTA tile 128(M) x 128(N) x 64(K); 4 warps (2x2) of 64x64; 3-stage cp.async.
// TWO CTAs per SM. Grid mapping: blockIdx.x -> M, blockIdx.y -> N so that
// consecutive (co-scheduled) CTAs share the SAME B slice -> B stays L2-hot.
// Rows are 64 halves (128B) padded to 144B: conflict-free stores + ldmatrix.
// ---------------------------------------------------------------------------
static constexpr int MT = 128;
static constexpr int NT = 128;
static constexpr int KC = 64;                      // halves of K per chunk (128B/row)
static constexpr int STAGES = 3;
static constexpr int THREADS = 128;
static constexpr int ROWB = 144;                   // padded row stride in bytes
static constexpr int A_BYTES = MT * ROWB;          // 18432
static constexpr int B_BYTES = NT * ROWB;          // 18432
static constexpr int BUF     = A_BYTES + B_BYTES;  // 36864
static constexpr int SMEM_TOTAL = STAGES * BUF;    // 110592 (x2 CTAs = 221184 < 227KB)

__device__ __forceinline__ void load_chunk(uint32_t bufb,
                                           const __half* __restrict__ A,
                                           const __half* __restrict__ Bm,
                                           int mbase, int nbase, int K, int kc, int tid) {
    const int kofs = kc * KC;
#pragma unroll
    for (int i = 0; i < 8; i++) {                  // A: 128 rows x 8 segs / 128 thr
        int j = tid + (i << 7);
        int r = j >> 3, s = j & 7;
        const __half* src = A + (size_t)(mbase + r) * K + kofs + s * 8;
        CP_ASYNC16(bufb + (uint32_t)(r * ROWB + s * 16), src);
    }
#pragma unroll
    for (int i = 0; i < 8; i++) {                  // B: 128 rows x 8 segs / 128 thr
        int j = tid + (i << 7);
        int r = j >> 3, s = j & 7;
        const __half* src = Bm + (size_t)(nbase + r) * K + kofs + s * 8;
        CP_ASYNC16(bufb + (uint32_t)A_BYTES + (uint32_t)(r * ROWB + s * 16), src);
    }
}

// load fragments for one k16 step (4 A tiles m16k16, 4 B tiles n16k16)
__device__ __forceinline__ void load_frags(uint32_t bufb, uint32_t a_lane, uint32_t b_lane,
                                           int ks, uint32_t a[4][4], uint32_t b[4][4]) {
    const uint32_t boff = (uint32_t)(ks * 32);     // 16 halves = 32B per k16 step
#pragma unroll
    for (int mt = 0; mt < 4; mt++)
        ldsm_x4(a[mt], bufb + a_lane + (uint32_t)(mt * 16 * ROWB) + boff);
#pragma unroll
    for (int np = 0; np < 4; np++)
        ldsm_x4(b[np], bufb + b_lane + (uint32_t)(np * 16 * ROWB) + boff);
}

__global__ void __launch_bounds__(THREADS, 2)
gemm_f16_mma(const __half* __restrict__ A, const __half* __restrict__ Bm,
             const float* __restrict__ bias, float* __restrict__ C,
             int M, int N, int K) {
    extern __shared__ __align__(16) char smem[];
    const uint32_t sb = smem_u32(smem);
    const int tid = threadIdx.x;
    const int wid = tid >> 5;
    const int l   = tid & 31;
    const int wm  = wid >> 1;          // 0..1  (M warp row, 64 rows each)
    const int wn  = wid & 1;           // 0..1  (N warp col, 64 cols each)
    const int mbase = blockIdx.x * MT; // bx -> M: co-resident CTAs share B slice
    const int nbase = blockIdx.y * NT;

    // ldmatrix lane->address: lanes 0-15 rows 0-15 (k0-7), 16-31 same rows (k8-15)
    const int      lrow = (l & 7) + ((l >> 3) & 1) * 8;
    const uint32_t lhi  = (uint32_t)((l >> 4) * 16);
    const uint32_t a_lane = (uint32_t)((wm * 64 + lrow) * ROWB) + lhi;
    const uint32_t b_lane = (uint32_t)A_BYTES + (uint32_t)((wn * 64 + lrow) * ROWB) + lhi;

    float c[4][8][4];
#pragma unroll
    for (int mt = 0; mt < 4; mt++)
#pragma unroll
        for (int nt = 0; nt < 8; nt++)
#pragma unroll
            for (int q = 0; q < 4; q++) c[mt][nt][q] = 0.0f;

    const int nch = K / KC;            // 16 for K=1024

    load_chunk(sb, A, Bm, mbase, nbase, K, 0, tid);
    CP_COMMIT();
    load_chunk(sb + BUF, A, Bm, mbase, nbase, K, 1, tid);
    CP_COMMIT();

    uint32_t afr[2][4][4], bfr[2][4][4];
    uint32_t slot = 0;
    for (int kc = 0; kc < nch; kc++) {
        CP_WAIT1();
        __syncthreads();
        const uint32_t bufb = sb + slot * BUF;
        if (kc + 2 < nch) {
            uint32_t ws = slot + 2; if (ws >= STAGES) ws -= STAGES;
            load_chunk(sb + ws * BUF, A, Bm, mbase, nbase, K, kc + 2, tid);
        }
        CP_COMMIT();

        load_frags(bufb, a_lane, b_lane, 0, afr[0], bfr[0]);
#pragma unroll
        for (int ks = 0; ks < 4; ks++) {           // 4 x k16 = K chunk of 64
            const int cur = ks & 1;
            if (ks < 3)
                load_frags(bufb, a_lane, b_lane, ks + 1, afr[cur ^ 1], bfr[cur ^ 1]);
#pragma unroll
            for (int mt = 0; mt < 4; mt++)
#pragma unroll
                for (int nt = 0; nt < 8; nt++) {
                    const int np = nt >> 1, od = nt & 1;
                    mma_f16(c[mt][nt], afr[cur][mt], bfr[cur][np][od], bfr[cur][np][2 + od]);
                }
        }
        slot++; if (slot >= STAGES) slot = 0;
    }

    // Epilogue: rows = mbase+wm*64+mt*16+{g,g+8}, cols = nbase+wn*64+nt*8+2t+{0,1}
    const int g = l >> 2, t = l & 3;
    const int row0 = mbase + wm * 64 + g;
    const int colb = nbase + wn * 64 + t * 2;
#pragma unroll
    for (int nt = 0; nt < 8; nt++) {
        float2 bv = make_float2(0.0f, 0.0f);
        if (bias) bv = *reinterpret_cast<const float2*>(bias + colb + nt * 8);
#pragma unroll
        for (int mt = 0; mt < 4; mt++) {
            const int r = row0 + mt * 16;
            float2 v0 = make_float2(c[mt][nt][0] + bv.x, c[mt][nt][1] + bv.y);
            float2 v1 = make_float2(c[mt][nt][2] + bv.x, c[mt][nt][3] + bv.y);
            *reinterpret_cast<float2*>(C + (size_t)r * N + colb + nt * 8)       = v0;
            *reinterpret_cast<float2*>(C + (size_t)(r + 8) * N + colb + nt * 8) = v1;
        }
    }
}

// ---------------------------------------------------------------------------
// Small kernels
// ---------------------------------------------------------------------------
__global__ void detect_kernel(const void* seq) {
    __shared__ int ok;
    if (threadIdx.x == 0) ok = 1;
    __syncthreads();
    const long long* p = (const long long*)seq;   // reads 16KB <= int32 buffer size
    for (int i = threadIdx.x; i < MROWS / 2; i += blockDim.x) {
        long long v = p[i];
        if (v < 0 || v >= VOCAB) ok = 0;
    }
    __syncthreads();
    if (threadIdx.x == 0) g_is64 = ok;
}

// gather fp32 embeddings -> fp16 A of GEMM1
__global__ void gather_kernel(const void* seq, const float* __restrict__ emb,
                              __half* __restrict__ e) {
    const int row  = blockIdx.x * 8 + (threadIdx.x >> 5);
    const int lane = threadIdx.x & 31;
    long long tok;
    if (g_is64) tok = ((const long long*)seq)[row];
    else        tok = (long long)((const int*)seq)[row];
    const float4* s = (const float4*)(emb + (size_t)tok * DIMS);
    __half2*      d = (__half2*)(e + (size_t)row * DIMS);
#pragma unroll
    for (int i = 0; i < 8; i++) {
        float4 v = s[lane + 32 * i];
        d[(lane + 32 * i) * 2 + 0] = __floats2half2_rn(v.x, v.y);
        d[(lane + 32 * i) * 2 + 1] = __floats2half2_rn(v.z, v.w);
    }
}

// fp32 weights -> fp16 (round-to-nearest); 2 float4 per thread for MLP
__global__ void cvt_kernel(const float* __restrict__ src, __half* __restrict__ dst) {
    const size_t i0 = ((size_t)blockIdx.x * blockDim.x + threadIdx.x) * 2;
    float4 v0 = reinterpret_cast<const float4*>(src)[i0];
    float4 v1 = reinterpret_cast<const float4*>(src)[i0 + 1];
    __half2 h[4];
    h[0] = __floats2half2_rn(v0.x, v0.y);
    h[1] = __floats2half2_rn(v0.z, v0.w);
    h[2] = __floats2half2_rn(v1.x, v1.y);
    h[3] = __floats2half2_rn(v1.z, v1.w);
    reinterpret_cast<float4*>(dst)[i0 >> 1] = *reinterpret_cast<float4*>(h);
}

// --- parallel causal cumulative mean: 2-pass segmented scan ----------------
__global__ void segsum_kernel(const float* __restrict__ V, float* __restrict__ S) {
    const int b   = blockIdx.x / SEGS;
    const int seg = blockIdx.x % SEGS;
    const int d   = threadIdx.x * 4;
    const float* vp = V + ((size_t)b * LL + (size_t)seg * SEGL) * DIMS + d;
    float4 acc = make_float4(0.f, 0.f, 0.f, 0.f);
#pragma unroll 8
    for (int lq = 0; lq < SEGL; lq++) {
        float4 v = *reinterpret_cast<const float4*>(vp + (size_t)lq * DIMS);
        acc.x += v.x; acc.y += v.y; acc.z += v.z; acc.w += v.w;
    }
    *reinterpret_cast<float4*>(S + ((size_t)b * SEGS + seg) * DIMS + d) = acc;
}

// prefix of segment sums + in-segment running mean -> fp16 A of GEMM2
__global__ void cummean_apply(const float* __restrict__ V, const float* __restrict__ S,
                              __half* __restrict__ avg) {
    const int b   = blockIdx.x / SEGS;
    const int seg = blockIdx.x % SEGS;
    const int d   = threadIdx.x * 4;
    float4 acc = make_float4(0.f, 0.f, 0.f, 0.f);
    for (int j = 0; j < seg; j++) {
        float4 s = *reinterpret_cast<const float4*>(S + ((size_t)b * SEGS + j) * DIMS + d);
        acc.x += s.x; acc.y += s.y; acc.z += s.z; acc.w += s.w;
    }
    const float* vp = V   + ((size_t)b * LL + (size_t)seg * SEGL) * DIMS + d;
    __half*      ap = avg + ((size_t)b * LL + (size_t)seg * SEGL) * DIMS + d;
#pragma unroll 4
    for (int lq = 0; lq < SEGL; lq++) {
        float4 v = *reinterpret_cast<const float4*>(vp + (size_t)lq * DIMS);
        acc.x += v.x; acc.y += v.y; acc.z += v.z; acc.w += v.w;
        const float inv = 1.0f / (float)(seg * SEGL + lq + 1);
        __half2 h0 = __floats2half2_rn(acc.x * inv, acc.y * inv);
        __half2 h1 = __floats2half2_rn(acc.z * inv, acc.w * inv);
        *reinterpret_cast<__half2*>(ap + (size_t)lq * DIMS + 0) = h0;
        *reinterpret_cast<__half2*>(ap + (size_t)lq * DIMS + 2) = h1;
    }
}

// ---------------------------------------------------------------------------
// Launch
// ---------------------------------------------------------------------------
extern "C" void kernel_launch(void* const* d_in, const int* in_sizes, int n_in,
                              void* d_out, int out_size) {
    const void*  seq = d_in[0];
    const float* emb = (const float*)d_in[1];
    const float* WV  = (const float*)d_in[2];
    const float* WO  = (const float*)d_in[3];
    const float* bo  = (const float*)d_in[4];
    float* out = (float*)d_out;

    cudaFuncSetAttribute(gemm_f16_mma,
                         cudaFuncAttributeMaxDynamicSharedMemorySize, SMEM_TOTAL);

    __half *ge, *ga, *gwv, *gwo;
    float *gv, *gs;
    cudaGetSymbolAddress((void**)&ge,  g_e);
    cudaGetSymbolAddress((void**)&gv,  g_V);
    cudaGetSymbolAddress((void**)&ga,  g_avg);
    cudaGetSymbolAddress((void**)&gwv, g_wv);
    cudaGetSymbolAddress((void**)&gwo, g_wo);
    cudaGetSymbolAddress((void**)&gs,  g_seg);

    detect_kernel<<<1, 256>>>(seq);
    gather_kernel<<<MROWS / 8, 256>>>(seq, emb, ge);
    cvt_kernel<<<(DIMS * DIMS) / 8 / 256, 256>>>(WV, gwv);
    cvt_kernel<<<(VOCAB * DIMS) / 8 / 256, 256>>>(WO, gwo);

    // GEMM1: V = e @ W_V^T   [4096 x 1024 x 1024]   (grid: x=M, y=N)
    gemm_f16_mma<<<dim3(MROWS / MT, DIMS / NT), THREADS, SMEM_TOTAL>>>(
        ge, gwv, nullptr, gv, MROWS, DIMS, DIMS);

    segsum_kernel<<<BB * SEGS, 256>>>(gv, gs);
    cummean_apply<<<BB * SEGS, 256>>>(gv, gs, ga);

    // GEMM2: out = avg @ W_out^T + b   [4096 x 32000 x 1024]   (grid: x=M, y=N)
    gemm_f16_mma<<<dim3(MROWS / MT, VOCAB / NT), THREADS, SMEM_TOTAL>>>(
        ga, gwo, bo, out, MROWS, VOCAB, DIMS);
}

// round 9
// speedup vs baseline: 2.5206x; 1.0001x over previous
#include <cuda_runtime.h>
#include <cuda_fp16.h>
#include <cstdint>

// ---------------------------------------------------------------------------
// Problem constants
// ---------------------------------------------------------------------------
static constexpr int VOCAB = 32000;
static constexpr int DIMS  = 1024;
static constexpr int BB    = 2;
static constexpr int LL    = 2048;
static constexpr int MROWS = BB * LL;          // 4096
static constexpr int SEGS  = 32;               // cummean scan segments
static constexpr int SEGL  = LL / SEGS;        // 64

// Scratch (static device globals: allocation-free)
// Restructure: cummean commutes with W_V projection (both linear), so we scan
// the gathered embeddings FIRST, then run both GEMMs back to back.
__device__ __half g_eavg[MROWS * DIMS];        // fp16 cummean(e)   (A of GEMM1)
__device__ __half g_avg [MROWS * DIMS];        // fp16 avg = cummean(e)@W_V^T (A of GEMM2)
__device__ __half g_wv  [DIMS * DIMS];         // fp16 W_V
__device__ __half g_wo  [VOCAB * DIMS];        // fp16 W_out
__device__ float  g_seg [BB * SEGS * DIMS];    // segment sums for scan
__device__ int    g_is64;

// ---------------------------------------------------------------------------
// PTX helpers (base sm_100-compatible: cp.async + ldmatrix + mma.sync fp16)
// ---------------------------------------------------------------------------
__device__ __forceinline__ uint32_t smem_u32(const void* p) {
    uint32_t a;
    asm("{ .reg .u64 t; cvta.to.shared.u64 t, %1; cvt.u32.u64 %0, t; }" : "=r"(a) : "l"(p));
    return a;
}

#define CP_ASYNC16(dst, src) \
    asm volatile("cp.async.cg.shared.global [%0], [%1], 16;" :: "r"(dst), "l"(src) : "memory")
#define CP_COMMIT() asm volatile("cp.async.commit_group;" ::: "memory")
#define CP_WAIT1()  asm volatile("cp.async.wait_group 1;" ::: "memory")

__device__ __forceinline__ void ldsm_x4(uint32_t* r, uint32_t addr) {
    asm volatile("ldmatrix.sync.aligned.m8n8.x4.shared.b16 {%0,%1,%2,%3}, [%4];"
                 : "=r"(r[0]), "=r"(r[1]), "=r"(r[2]), "=r"(r[3]) : "r"(addr));
}

// fp16 MMA, fp32 accumulate: D[16,8] += A[16,16] * B[16,8] (B col-major = N,K row)
__device__ __forceinline__ void mma_f16(float* c, const uint32_t* a,
                                        uint32_t b0, uint32_t b1) {
    asm volatile(
        "mma.sync.aligned.m16n8k16.row.col.f32.f16.f16.f32 "
        "{%0,%1,%2,%3}, {%4,%5,%6,%7}, {%8,%9}, {%0,%1,%2,%3};"
        : "+f"(c[0]), "+f"(c[1]), "+f"(c[2]), "+f"(c[3])
        : "r"(a[0]), "r"(a[1]), "r"(a[2]), "r"(a[3]), "r"(b0), "r"(b1));
}

// ---------------------------------------------------------------------------
// GEMM: C[M,N] = A[M,K] * B[N,K]^T (+bias), fp16 mma.sync, fp32 accumulate.
// CTA tile 128(M) x 128(N) x 64(K); 4 warps (2x2) of 64x64; 3-stage cp.async.
// TWO CTAs per SM; grid x->M so co-resident CTAs share the B slice (L2-hot).
// Output: fp32 to C, or fp16 to Ch when Ch != nullptr (fused convert).
// ---------------------------------------------------------------------------
static constexpr int MT = 128;
static constexpr int NT = 128;
static constexpr int KC = 64;                      // halves of K per chunk (128B/row)
static constexpr int STAGES = 3;
static constexpr int THREADS = 128;
static constexpr int ROWB = 144;                   // padded row stride in bytes
static constexpr int A_BYTES = MT * ROWB;          // 18432
static constexpr int B_BYTES = NT * ROWB;          // 18432
static constexpr int BUF     = A_BYTES + B_BYTES;  // 36864
static constexpr int SMEM_TOTAL = STAGES * BUF;    // 110592 (x2 CTAs = 221184 < 227KB)

__device__ __forceinline__ void load_chunk(uint32_t bufb,
                                           const __half* __restrict__ A,
                                           const __half* __restrict__ Bm,
                                           int mbase, int nbase, int K, int kc, int tid) {
    const int kofs = kc * KC;
#pragma unroll
    for (int i = 0; i < 8; i++) {                  // A: 128 rows x 8 segs / 128 thr
        int j = tid + (i << 7);
        int r = j >> 3, s = j & 7;
        const __half* src = A + (size_t)(mbase + r) * K + kofs + s * 8;
        CP_ASYNC16(bufb + (uint32_t)(r * ROWB + s * 16), src);
    }
#pragma unroll
    for (int i = 0; i < 8; i++) {                  // B: 128 rows x 8 segs / 128 thr
        int j = tid + (i << 7);
        int r = j >> 3, s = j & 7;
        const __half* src = Bm + (size_t)(nbase + r) * K + kofs + s * 8;
        CP_ASYNC16(bufb + (uint32_t)A_BYTES + (uint32_t)(r * ROWB + s * 16), src);
    }
}

// load fragments for one k16 step (4 A tiles m16k16, 4 B tiles n16k16)
__device__ __forceinline__ void load_frags(uint32_t bufb, uint32_t a_lane, uint32_t b_lane,
                                           int ks, uint32_t a[4][4], uint32_t b[4][4]) {
    const uint32_t boff = (uint32_t)(ks * 32);     // 16 halves = 32B per k16 step
#pragma unroll
    for (int mt = 0; mt < 4; mt++)
        ldsm_x4(a[mt], bufb + a_lane + (uint32_t)(mt * 16 * ROWB) + boff);
#pragma unroll
    for (int np = 0; np < 4; np++)
        ldsm_x4(b[np], bufb + b_lane + (uint32_t)(np * 16 * ROWB) + boff);
}

__global__ void __launch_bounds__(THREADS, 2)
gemm_f16_mma(const __half* __restrict__ A, const __half* __restrict__ Bm,
             const float* __restrict__ bias, float* __restrict__ C,
             __half* __restrict__ Ch, int M, int N, int K) {
    extern __shared__ __align__(16) char smem[];
    const uint32_t sb = smem_u32(smem);
    const int tid = threadIdx.x;
    const int wid = tid >> 5;
    const int l   = tid & 31;
    const int wm  = wid >> 1;          // 0..1  (M warp row, 64 rows each)
    const int wn  = wid & 1;           // 0..1  (N warp col, 64 cols each)
    const int mbase = blockIdx.x * MT; // bx -> M: co-resident CTAs share B slice
    const int nbase = blockIdx.y * NT;

    const int      lrow = (l & 7) + ((l >> 3) & 1) * 8;
    const uint32_t lhi  = (uint32_t)((l >> 4) * 16);
    const uint32_t a_lane = (uint32_t)((wm * 64 + lrow) * ROWB) + lhi;
    const uint32_t b_lane = (uint32_t)A_BYTES + (uint32_t)((wn * 64 + lrow) * ROWB) + lhi;

    float c[4][8][4];
#pragma unroll
    for (int mt = 0; mt < 4; mt++)
#pragma unroll
        for (int nt = 0; nt < 8; nt++)
#pragma unroll
            for (int q = 0; q < 4; q++) c[mt][nt][q] = 0.0f;

    const int nch = K / KC;            // 16 for K=1024

    load_chunk(sb, A, Bm, mbase, nbase, K, 0, tid);
    CP_COMMIT();
    load_chunk(sb + BUF, A, Bm, mbase, nbase, K, 1, tid);
    CP_COMMIT();

    uint32_t afr[2][4][4], bfr[2][4][4];
    uint32_t slot = 0;
    for (int kc = 0; kc < nch; kc++) {
        CP_WAIT1();
        __syncthreads();
        const uint32_t bufb = sb + slot * BUF;
        if (kc + 2 < nch) {
            uint32_t ws = slot + 2; if (ws >= STAGES) ws -= STAGES;
            load_chunk(sb + ws * BUF, A, Bm, mbase, nbase, K, kc + 2, tid);
        }
        CP_COMMIT();

        load_frags(bufb, a_lane, b_lane, 0, afr[0], bfr[0]);
#pragma unroll
        for (int ks = 0; ks < 4; ks++) {           // 4 x k16 = K chunk of 64
            const int cur = ks & 1;
            if (ks < 3)
                load_frags(bufb, a_lane, b_lane, ks + 1, afr[cur ^ 1], bfr[cur ^ 1]);
#pragma unroll
            for (int mt = 0; mt < 4; mt++)
#pragma unroll
                for (int nt = 0; nt < 8; nt++) {
                    const int np = nt >> 1, od = nt & 1;
                    mma_f16(c[mt][nt], afr[cur][mt], bfr[cur][np][od], bfr[cur][np][2 + od]);
                }
        }
        slot++; if (slot >= STAGES) slot = 0;
    }

    // Epilogue: rows = mbase+wm*64+mt*16+{g,g+8}, cols = nbase+wn*64+nt*8+2t+{0,1}
    const int g = l >> 2, t = l & 3;
    const int row0 = mbase + wm * 64 + g;
    const int colb = nbase + wn * 64 + t * 2;
#pragma unroll
    for (int nt = 0; nt < 8; nt++) {
        float2 bv = make_float2(0.0f, 0.0f);
        if (bias) bv = *reinterpret_cast<const float2*>(bias + colb + nt * 8);
#pragma unroll
        for (int mt = 0; mt < 4; mt++) {
            const int r = row0 + mt * 16;
            float2 v0 = make_float2(c[mt][nt][0] + bv.x, c[mt][nt][1] + bv.y);
            float2 v1 = make_float2(c[mt][nt][2] + bv.x, c[mt][nt][3] + bv.y);
            if (Ch) {
                *reinterpret_cast<__half2*>(Ch + (size_t)r * N + colb + nt * 8)
                    = __floats2half2_rn(v0.x, v0.y);
                *reinterpret_cast<__half2*>(Ch + (size_t)(r + 8) * N + colb + nt * 8)
                    = __floats2half2_rn(v1.x, v1.y);
            } else {
                *reinterpret_cast<float2*>(C + (size_t)r * N + colb + nt * 8)       = v0;
                *reinterpret_cast<float2*>(C + (size_t)(r + 8) * N + colb + nt * 8) = v1;
            }
        }
    }
}

// ---------------------------------------------------------------------------
// Small kernels
// ---------------------------------------------------------------------------
__global__ void detect_kernel(const void* seq) {
    __shared__ int ok;
    if (threadIdx.x == 0) ok = 1;
    __syncthreads();
    const long long* p = (const long long*)seq;   // reads 16KB <= int32 buffer size
    for (int i = threadIdx.x; i < MROWS / 2; i += blockDim.x) {
        long long v = p[i];
        if (v < 0 || v >= VOCAB) ok = 0;
    }
    __syncthreads();
    if (threadIdx.x == 0) g_is64 = ok;
}

__device__ __forceinline__ long long get_tok(const void* seq, int idx) {
    if (g_is64) return ((const long long*)seq)[idx];
    return (long long)((const int*)seq)[idx];
}

// fp32 weights -> fp16 (round-to-nearest); 2 float4 per thread for MLP
__global__ void cvt_kernel(const float* __restrict__ src, __half* __restrict__ dst) {
    const size_t i0 = ((size_t)blockIdx.x * blockDim.x + threadIdx.x) * 2;
    float4 v0 = reinterpret_cast<const float4*>(src)[i0];
    float4 v1 = reinterpret_cast<const float4*>(src)[i0 + 1];
    __half2 h[4];
    h[0] = __floats2half2_rn(v0.x, v0.y);
    h[1] = __floats2half2_rn(v0.z, v0.w);
    h[2] = __floats2half2_rn(v1.x, v1.y);
    h[3] = __floats2half2_rn(v1.z, v1.w);
    reinterpret_cast<float4*>(dst)[i0 >> 1] = *reinterpret_cast<float4*>(h);
}

// --- fused gather + causal cumulative mean over EMBEDDINGS (scan-first) ----
// pass 1: per-(b,seg) sums of gathered embedding rows (fp32)
__global__ void segsum_emb(const void* __restrict__ seq, const float* __restrict__ emb,
                           float* __restrict__ S) {
    const int b   = blockIdx.x / SEGS;
    const int seg = blockIdx.x % SEGS;
    const int d   = threadIdx.x * 4;
    const int lbase = b * LL + seg * SEGL;
    float4 acc = make_float4(0.f, 0.f, 0.f, 0.f);
#pragma unroll 4
    for (int lq = 0; lq < SEGL; lq++) {
        const long long tok = get_tok(seq, lbase + lq);
        float4 v = *reinterpret_cast<const float4*>(emb + (size_t)tok * DIMS + d);
        acc.x += v.x; acc.y += v.y; acc.z += v.z; acc.w += v.w;
    }
    *reinterpret_cast<float4*>(S + ((size_t)b * SEGS + seg) * DIMS + d) = acc;
}

// pass 2: prefix of segment sums + in-segment running mean -> fp16 cummean(e)
__global__ void cummean_emb(const void* __restrict__ seq, const float* __restrict__ emb,
                            const float* __restrict__ S, __half* __restrict__ eavg) {
    const int b   = blockIdx.x / SEGS;
    const int seg = blockIdx.x % SEGS;
    const int d   = threadIdx.x * 4;
    float4 acc = make_float4(0.f, 0.f, 0.f, 0.f);
    for (int j = 0; j < seg; j++) {
        float4 s = *reinterpret_cast<const float4*>(S + ((size_t)b * SEGS + j) * DIMS + d);
        acc.x += s.x; acc.y += s.y; acc.z += s.z; acc.w += s.w;
    }
    const int lbase = b * LL + seg * SEGL;
    __half* ap = eavg + (size_t)lbase * DIMS + d;
#pragma unroll 4
    for (int lq = 0; lq < SEGL; lq++) {
        const long long tok = get_tok(seq, lbase + lq);
        float4 v = *reinterpret_cast<const float4*>(emb + (size_t)tok * DIMS + d);
        acc.x += v.x; acc.y += v.y; acc.z += v.z; acc.w += v.w;
        const float inv = 1.0f / (float)(seg * SEGL + lq + 1);
        *reinterpret_cast<__half2*>(ap + (size_t)lq * DIMS + 0)
            = __floats2half2_rn(acc.x * inv, acc.y * inv);
        *reinterpret_cast<__half2*>(ap + (size_t)lq * DIMS + 2)
            = __floats2half2_rn(acc.z * inv, acc.w * inv);
    }
}

// ---------------------------------------------------------------------------
// Launch
// ---------------------------------------------------------------------------
extern "C" void kernel_launch(void* const* d_in, const int* in_sizes, int n_in,
                              void* d_out, int out_size) {
    const void*  seq = d_in[0];
    const float* emb = (const float*)d_in[1];
    const float* WV  = (const float*)d_in[2];
    const float* WO  = (const float*)d_in[3];
    const float* bo  = (const float*)d_in[4];
    float* out = (float*)d_out;

    cudaFuncSetAttribute(gemm_f16_mma,
                         cudaFuncAttributeMaxDynamicSharedMemorySize, SMEM_TOTAL);

    __half *gea, *ga, *gwv, *gwo;
    float *gs;
    cudaGetSymbolAddress((void**)&gea, g_eavg);
    cudaGetSymbolAddress((void**)&ga,  g_avg);
    cudaGetSymbolAddress((void**)&gwv, g_wv);
    cudaGetSymbolAddress((void**)&gwo, g_wo);
    cudaGetSymbolAddress((void**)&gs,  g_seg);

    detect_kernel<<<1, 256>>>(seq);
    cvt_kernel<<<(DIMS * DIMS) / 8 / 256, 256>>>(WV, gwv);
    cvt_kernel<<<(VOCAB * DIMS) / 8 / 256, 256>>>(WO, gwo);

    // scan-first: cummean(e) directly from gathered embeddings
    segsum_emb<<<BB * SEGS, 256>>>(seq, emb, gs);
    cummean_emb<<<BB * SEGS, 256>>>(seq, emb, gs, gea);

    // GEMM1: avg = cummean(e) @ W_V^T   [4096 x 1024 x 1024], fp16 output
    gemm_f16_mma<<<dim3(MROWS / MT, DIMS / NT), THREADS, SMEM_TOTAL>>>(
        gea, gwv, nullptr, nullptr, ga, MROWS, DIMS, DIMS);

    // GEMM2: out = avg @ W_out^T + b   [4096 x 32000 x 1024], fp32 output
    gemm_f16_mma<<<dim3(MROWS / MT, VOCAB / NT), THREADS, SMEM_TOTAL>>>(
        ga, gwo, bo, out, nullptr, MROWS, VOCAB, DIMS);
}

// round 10
// speedup vs baseline: 2.5250x; 1.0018x over previous
#include <cuda_runtime.h>
#include <cuda_fp16.h>
#include <cstdint>

// ---------------------------------------------------------------------------
// Problem constants
// ---------------------------------------------------------------------------
static constexpr int VOCAB = 32000;
static constexpr int DIMS  = 1024;
static constexpr int BB    = 2;
static constexpr int LL    = 2048;
static constexpr int MROWS = BB * LL;          // 4096
static constexpr int SEGS  = 128;              // cummean scan segments (full-chip grid)
static constexpr int SEGL  = LL / SEGS;        // 16

// Scratch (static device globals: allocation-free)
// cummean commutes with the W_V projection (both linear): scan first, then GEMMs.
__device__ __half g_eavg[MROWS * DIMS];        // fp16 cummean(e)   (A of GEMM1)
__device__ __half g_avg [MROWS * DIMS];        // fp16 avg = cummean(e)@W_V^T (A of GEMM2)
__device__ __half g_wv  [DIMS * DIMS];         // fp16 W_V
__device__ __half g_wo  [VOCAB * DIMS];        // fp16 W_out
__device__ float  g_seg [BB * SEGS * DIMS];    // segment sums for scan
__device__ int    g_is64;

// ---------------------------------------------------------------------------
// PTX helpers (base sm_100-compatible: cp.async + ldmatrix + mma.sync fp16)
// ---------------------------------------------------------------------------
__device__ __forceinline__ uint32_t smem_u32(const void* p) {
    uint32_t a;
    asm("{ .reg .u64 t; cvta.to.shared.u64 t, %1; cvt.u32.u64 %0, t; }" : "=r"(a) : "l"(p));
    return a;
}

#define CP_ASYNC16(dst, src) \
    asm volatile("cp.async.cg.shared.global [%0], [%1], 16;" :: "r"(dst), "l"(src) : "memory")
#define CP_COMMIT() asm volatile("cp.async.commit_group;" ::: "memory")
#define CP_WAIT1()  asm volatile("cp.async.wait_group 1;" ::: "memory")

__device__ __forceinline__ void ldsm_x4(uint32_t* r, uint32_t addr) {
    asm volatile("ldmatrix.sync.aligned.m8n8.x4.shared.b16 {%0,%1,%2,%3}, [%4];"
                 : "=r"(r[0]), "=r"(r[1]), "=r"(r[2]), "=r"(r[3]) : "r"(addr));
}

// fp16 MMA, fp32 accumulate: D[16,8] += A[16,16] * B[16,8] (B col-major = N,K row)
__device__ __forceinline__ void mma_f16(float* c, const uint32_t* a,
                                        uint32_t b0, uint32_t b1) {
    asm volatile(
        "mma.sync.aligned.m16n8k16.row.col.f32.f16.f16.f32 "
        "{%0,%1,%2,%3}, {%4,%5,%6,%7}, {%8,%9}, {%0,%1,%2,%3};"
        : "+f"(c[0]), "+f"(c[1]), "+f"(c[2]), "+f"(c[3])
        : "r"(a[0]), "r"(a[1]), "r"(a[2]), "r"(a[3]), "r"(b0), "r"(b1));
}

// ---------------------------------------------------------------------------
// GEMM: C[M,N] = A[M,K] * B[N,K]^T (+bias), fp16 mma.sync, fp32 accumulate.
// CTA tile 128(M) x 128(N) x 64(K); 4 warps (2x2) of 64x64; 3-stage cp.async.
// TWO CTAs per SM; grid x->M so co-resident CTAs share the B slice (L2-hot).
// Output dtype chosen at COMPILE time (OUT_HALF template).
// ---------------------------------------------------------------------------
static constexpr int MT = 128;
static constexpr int NT = 128;
static constexpr int KC = 64;                      // halves of K per chunk (128B/row)
static constexpr int STAGES = 3;
static constexpr int THREADS = 128;
static constexpr int ROWB = 144;                   // padded row stride in bytes
static constexpr int A_BYTES = MT * ROWB;          // 18432
static constexpr int B_BYTES = NT * ROWB;          // 18432
static constexpr int BUF     = A_BYTES + B_BYTES;  // 36864
static constexpr int SMEM_TOTAL = STAGES * BUF;    // 110592 (x2 CTAs = 221184 < 227KB)

__device__ __forceinline__ void load_chunk(uint32_t bufb,
                                           const __half* __restrict__ A,
                                           const __half* __restrict__ Bm,
                                           int mbase, int nbase, int K, int kc, int tid) {
    const int kofs = kc * KC;
#pragma unroll
    for (int i = 0; i < 8; i++) {                  // A: 128 rows x 8 segs / 128 thr
        int j = tid + (i << 7);
        int r = j >> 3, s = j & 7;
        const __half* src = A + (size_t)(mbase + r) * K + kofs + s * 8;
        CP_ASYNC16(bufb + (uint32_t)(r * ROWB + s * 16), src);
    }
#pragma unroll
    for (int i = 0; i < 8; i++) {                  // B: 128 rows x 8 segs / 128 thr
        int j = tid + (i << 7);
        int r = j >> 3, s = j & 7;
        const __half* src = Bm + (size_t)(nbase + r) * K + kofs + s * 8;
        CP_ASYNC16(bufb + (uint32_t)A_BYTES + (uint32_t)(r * ROWB + s * 16), src);
    }
}

// load fragments for one k16 step (4 A tiles m16k16, 4 B tiles n16k16)
__device__ __forceinline__ void load_frags(uint32_t bufb, uint32_t a_lane, uint32_t b_lane,
                                           int ks, uint32_t a[4][4], uint32_t b[4][4]) {
    const uint32_t boff = (uint32_t)(ks * 32);     // 16 halves = 32B per k16 step
#pragma unroll
    for (int mt = 0; mt < 4; mt++)
        ldsm_x4(a[mt], bufb + a_lane + (uint32_t)(mt * 16 * ROWB) + boff);
#pragma unroll
    for (int np = 0; np < 4; np++)
        ldsm_x4(b[np], bufb + b_lane + (uint32_t)(np * 16 * ROWB) + boff);
}

template <bool OUT_HALF>
__global__ void __launch_bounds__(THREADS, 2)
gemm_f16_mma(const __half* __restrict__ A, const __half* __restrict__ Bm,
             const float* __restrict__ bias, float* __restrict__ C,
             __half* __restrict__ Ch, int M, int N, int K) {
    extern __shared__ __align__(16) char smem[];
    const uint32_t sb = smem_u32(smem);
    const int tid = threadIdx.x;
    const int wid = tid >> 5;
    const int l   = tid & 31;
    const int wm  = wid >> 1;          // 0..1  (M warp row, 64 rows each)
    const int wn  = wid & 1;           // 0..1  (N warp col, 64 cols each)
    const int mbase = blockIdx.x * MT; // bx -> M: co-resident CTAs share B slice
    const int nbase = blockIdx.y * NT;

    const int      lrow = (l & 7) + ((l >> 3) & 1) * 8;
    const uint32_t lhi  = (uint32_t)((l >> 4) * 16);
    const uint32_t a_lane = (uint32_t)((wm * 64 + lrow) * ROWB) + lhi;
    const uint32_t b_lane = (uint32_t)A_BYTES + (uint32_t)((wn * 64 + lrow) * ROWB) + lhi;

    float c[4][8][4];
#pragma unroll
    for (int mt = 0; mt < 4; mt++)
#pragma unroll
        for (int nt = 0; nt < 8; nt++)
#pragma unroll
            for (int q = 0; q < 4; q++) c[mt][nt][q] = 0.0f;

    const int nch = K / KC;            // 16 for K=1024

    load_chunk(sb, A, Bm, mbase, nbase, K, 0, tid);
    CP_COMMIT();
    load_chunk(sb + BUF, A, Bm, mbase, nbase, K, 1, tid);
    CP_COMMIT();

    uint32_t afr[2][4][4], bfr[2][4][4];
    uint32_t slot = 0;
    for (int kc = 0; kc < nch; kc++) {
        CP_WAIT1();
        __syncthreads();
        const uint32_t bufb = sb + slot * BUF;
        if (kc + 2 < nch) {
            uint32_t ws = slot + 2; if (ws >= STAGES) ws -= STAGES;
            load_chunk(sb + ws * BUF, A, Bm, mbase, nbase, K, kc + 2, tid);
        }
        CP_COMMIT();

        load_frags(bufb, a_lane, b_lane, 0, afr[0], bfr[0]);
#pragma unroll
        for (int ks = 0; ks < 4; ks++) {           // 4 x k16 = K chunk of 64
            const int cur = ks & 1;
            if (ks < 3)
                load_frags(bufb, a_lane, b_lane, ks + 1, afr[cur ^ 1], bfr[cur ^ 1]);
#pragma unroll
            for (int mt = 0; mt < 4; mt++)
#pragma unroll
                for (int nt = 0; nt < 8; nt++) {
                    const int np = nt >> 1, od = nt & 1;
                    mma_f16(c[mt][nt], afr[cur][mt], bfr[cur][np][od], bfr[cur][np][2 + od]);
                }
        }
        slot++; if (slot >= STAGES) slot = 0;
    }

    // Epilogue: rows = mbase+wm*64+mt*16+{g,g+8}, cols = nbase+wn*64+nt*8+2t+{0,1}
    const int g = l >> 2, t = l & 3;
    const int row0 = mbase + wm * 64 + g;
    const int colb = nbase + wn * 64 + t * 2;
#pragma unroll
    for (int nt = 0; nt < 8; nt++) {
        float2 bv = make_float2(0.0f, 0.0f);
        if (bias) bv = *reinterpret_cast<const float2*>(bias + colb + nt * 8);
#pragma unroll
        for (int mt = 0; mt < 4; mt++) {
            const int r = row0 + mt * 16;
            float2 v0 = make_float2(c[mt][nt][0] + bv.x, c[mt][nt][1] + bv.y);
            float2 v1 = make_float2(c[mt][nt][2] + bv.x, c[mt][nt][3] + bv.y);
            if (OUT_HALF) {
                *reinterpret_cast<__half2*>(Ch + (size_t)r * N + colb + nt * 8)
                    = __floats2half2_rn(v0.x, v0.y);
                *reinterpret_cast<__half2*>(Ch + (size_t)(r + 8) * N + colb + nt * 8)
                    = __floats2half2_rn(v1.x, v1.y);
            } else {
                *reinterpret_cast<float2*>(C + (size_t)r * N + colb + nt * 8)       = v0;
                *reinterpret_cast<float2*>(C + (size_t)(r + 8) * N + colb + nt * 8) = v1;
            }
        }
    }
}

// ---------------------------------------------------------------------------
// Small kernels
// ---------------------------------------------------------------------------
__global__ void detect_kernel(const void* seq) {
    __shared__ int ok;
    if (threadIdx.x == 0) ok = 1;
    __syncthreads();
    const long long* p = (const long long*)seq;   // reads 16KB <= int32 buffer size
    for (int i = threadIdx.x; i < MROWS / 2; i += blockDim.x) {
        long long v = p[i];
        if (v < 0 || v >= VOCAB) ok = 0;
    }
    __syncthreads();
    if (threadIdx.x == 0) g_is64 = ok;
}

__device__ __forceinline__ long long get_tok(const void* seq, int idx) {
    if (g_is64) return ((const long long*)seq)[idx];
    return (long long)((const int*)seq)[idx];
}

// fp32 weights -> fp16 (round-to-nearest); 2 float4 per thread for MLP
__global__ void cvt_kernel(const float* __restrict__ src, __half* __restrict__ dst) {
    const size_t i0 = ((size_t)blockIdx.x * blockDim.x + threadIdx.x) * 2;
    float4 v0 = reinterpret_cast<const float4*>(src)[i0];
    float4 v1 = reinterpret_cast<const float4*>(src)[i0 + 1];
    __half2 h[4];
    h[0] = __floats2half2_rn(v0.x, v0.y);
    h[1] = __floats2half2_rn(v0.z, v0.w);
    h[2] = __floats2half2_rn(v1.x, v1.y);
    h[3] = __floats2half2_rn(v1.z, v1.w);
    reinterpret_cast<float4*>(dst)[i0 >> 1] = *reinterpret_cast<float4*>(h);
}

// --- fused gather + causal cumulative mean over EMBEDDINGS (scan-first) ----
// pass 1: per-(b,seg) sums of gathered embedding rows (fp32); 256 blocks
__global__ void segsum_emb(const void* __restrict__ seq, const float* __restrict__ emb,
                           float* __restrict__ S) {
    const int b   = blockIdx.x / SEGS;
    const int seg = blockIdx.x % SEGS;
    const int d   = threadIdx.x * 4;
    const int lbase = b * LL + seg * SEGL;
    float4 acc = make_float4(0.f, 0.f, 0.f, 0.f);
#pragma unroll
    for (int lq = 0; lq < SEGL; lq++) {
        const long long tok = get_tok(seq, lbase + lq);
        float4 v = *reinterpret_cast<const float4*>(emb + (size_t)tok * DIMS + d);
        acc.x += v.x; acc.y += v.y; acc.z += v.z; acc.w += v.w;
    }
    *reinterpret_cast<float4*>(S + ((size_t)b * SEGS + seg) * DIMS + d) = acc;
}

// pass 2: prefix of segment sums (4-way MLP) + in-segment running mean -> fp16
__global__ void cummean_emb(const void* __restrict__ seq, const float* __restrict__ emb,
                            const float* __restrict__ S, __half* __restrict__ eavg) {
    const int b   = blockIdx.x / SEGS;
    const int seg = blockIdx.x % SEGS;
    const int d   = threadIdx.x * 4;
    // 4 independent accumulators over the prefix for memory-level parallelism
    float4 a0 = make_float4(0.f, 0.f, 0.f, 0.f);
    float4 a1 = a0, a2 = a0, a3 = a0;
    const float* Sp = S + (size_t)b * SEGS * DIMS + d;
    int j = 0;
    for (; j + 4 <= seg; j += 4) {
        float4 s0 = *reinterpret_cast<const float4*>(Sp + (size_t)(j + 0) * DIMS);
        float4 s1 = *reinterpret_cast<const float4*>(Sp + (size_t)(j + 1) * DIMS);
        float4 s2 = *reinterpret_cast<const float4*>(Sp + (size_t)(j + 2) * DIMS);
        float4 s3 = *reinterpret_cast<const float4*>(Sp + (size_t)(j + 3) * DIMS);
        a0.x += s0.x; a0.y += s0.y; a0.z += s0.z; a0.w += s0.w;
        a1.x += s1.x; a1.y += s1.y; a1.z += s1.z; a1.w += s1.w;
        a2.x += s2.x; a2.y += s2.y; a2.z += s2.z; a2.w += s2.w;
        a3.x += s3.x; a3.y += s3.y; a3.z += s3.z; a3.w += s3.w;
    }
    for (; j < seg; j++) {
        float4 s0 = *reinterpret_cast<const float4*>(Sp + (size_t)j * DIMS);
        a0.x += s0.x; a0.y += s0.y; a0.z += s0.z; a0.w += s0.w;
    }
    float4 acc;
    acc.x = (a0.x + a1.x) + (a2.x + a3.x);
    acc.y = (a0.y + a1.y) + (a2.y + a3.y);
    acc.z = (a0.z + a1.z) + (a2.z + a3.z);
    acc.w = (a0.w + a1.w) + (a2.w + a3.w);

    const int lbase = b * LL + seg * SEGL;
    __half* ap = eavg + (size_t)lbase * DIMS + d;
#pragma unroll
    for (int lq = 0; lq < SEGL; lq++) {
        const long long tok = get_tok(seq, lbase + lq);
        float4 v = *reinterpret_cast<const float4*>(emb + (size_t)tok * DIMS + d);
        acc.x += v.x; acc.y += v.y; acc.z += v.z; acc.w += v.w;
        const float inv = 1.0f / (float)(seg * SEGL + lq + 1);
        *reinterpret_cast<__half2*>(ap + (size_t)lq * DIMS + 0)
            = __floats2half2_rn(acc.x * inv, acc.y * inv);
        *reinterpret_cast<__half2*>(ap + (size_t)lq * DIMS + 2)
            = __floats2half2_rn(acc.z * inv, acc.w * inv);
    }
}

// ---------------------------------------------------------------------------
// Launch
// ---------------------------------------------------------------------------
extern "C" void kernel_launch(void* const* d_in, const int* in_sizes, int n_in,
                              void* d_out, int out_size) {
    const void*  seq = d_in[0];
    const float* emb = (const float*)d_in[1];
    const float* WV  = (const float*)d_in[2];
    const float* WO  = (const float*)d_in[3];
    const float* bo  = (const float*)d_in[4];
    float* out = (float*)d_out;

    cudaFuncSetAttribute(gemm_f16_mma<false>,
                         cudaFuncAttributeMaxDynamicSharedMemorySize, SMEM_TOTAL);
    cudaFuncSetAttribute(gemm_f16_mma<true>,
                         cudaFuncAttributeMaxDynamicSharedMemorySize, SMEM_TOTAL);

    __half *gea, *ga, *gwv, *gwo;
    float *gs;
    cudaGetSymbolAddress((void**)&gea, g_eavg);
    cudaGetSymbolAddress((void**)&ga,  g_avg);
    cudaGetSymbolAddress((void**)&gwv, g_wv);
    cudaGetSymbolAddress((void**)&gwo, g_wo);
    cudaGetSymbolAddress((void**)&gs,  g_seg);

    detect_kernel<<<1, 256>>>(seq);
    cvt_kernel<<<(DIMS * DIMS) / 8 / 256, 256>>>(WV, gwv);
    cvt_kernel<<<(VOCAB * DIMS) / 8 / 256, 256>>>(WO, gwo);

    // scan-first: cummean(e) directly from gathered embeddings (256-block grids)
    segsum_emb<<<BB * SEGS, 256>>>(seq, emb, gs);
    cummean_emb<<<BB * SEGS, 256>>>(seq, emb, gs, gea);

    // GEMM1: avg = cummean(e) @ W_V^T   [4096 x 1024 x 1024], fp16 output
    gemm_f16_mma<true><<<dim3(MROWS / MT, DIMS / NT), THREADS, SMEM_TOTAL>>>(
        gea, gwv, nullptr, nullptr, ga, MROWS, DIMS, DIMS);

    // GEMM2: out = avg @ W_out^T + b   [4096 x 32000 x 1024], fp32 output
    gemm_f16_mma<false><<<dim3(MROWS / MT, VOCAB / NT), THREADS, SMEM_TOTAL>>>(
        ga, gwo, bo, out, nullptr, MROWS, VOCAB, DIMS);
}

// round 11
// speedup vs baseline: 2.5451x; 1.0080x over previous
#include <cuda_runtime.h>
#include <cuda_fp16.h>
#include <cstdint>

// ---------------------------------------------------------------------------
// Problem constants
// ---------------------------------------------------------------------------
static constexpr int VOCAB = 32000;
static constexpr int DIMS  = 1024;
static constexpr int BB    = 2;
static constexpr int LL    = 2048;
static constexpr int MROWS = BB * LL;          // 4096
static constexpr int SEGS  = 128;              // cummean scan segments
static constexpr int SEGL  = LL / SEGS;        // 16
static constexpr int DCH   = 2;                // dim chunks per (b,seg) scan block

// Scratch (static device globals: allocation-free)
// cummean commutes with the W_V projection (both linear): scan first, then GEMMs.
__device__ __half g_eavg[MROWS * DIMS];        // fp16 cummean(e)   (A of GEMM1)
__device__ __half g_avg [MROWS * DIMS];        // fp16 avg = cummean(e)@W_V^T (A of GEMM2)
__device__ __half g_wv  [DIMS * DIMS];         // fp16 W_V
__device__ __half g_wo  [VOCAB * DIMS];        // fp16 W_out
__device__ float  g_seg [BB * SEGS * DIMS];    // segment sums for scan
__device__ int    g_is64;

// ---------------------------------------------------------------------------
// PTX helpers (base sm_100-compatible: cp.async + ldmatrix + mma.sync fp16)
// ---------------------------------------------------------------------------
__device__ __forceinline__ uint32_t smem_u32(const void* p) {
    uint32_t a;
    asm("{ .reg .u64 t; cvta.to.shared.u64 t, %1; cvt.u32.u64 %0, t; }" : "=r"(a) : "l"(p));
    return a;
}

#define CP_ASYNC16(dst, src) \
    asm volatile("cp.async.cg.shared.global [%0], [%1], 16;" :: "r"(dst), "l"(src) : "memory")
#define CP_COMMIT() asm volatile("cp.async.commit_group;" ::: "memory")
#define CP_WAIT1()  asm volatile("cp.async.wait_group 1;" ::: "memory")

__device__ __forceinline__ void ldsm_x4(uint32_t* r, uint32_t addr) {
    asm volatile("ldmatrix.sync.aligned.m8n8.x4.shared.b16 {%0,%1,%2,%3}, [%4];"
                 : "=r"(r[0]), "=r"(r[1]), "=r"(r[2]), "=r"(r[3]) : "r"(addr));
}

// fp16 MMA, fp32 accumulate: D[16,8] += A[16,16] * B[16,8] (B col-major = N,K row)
__device__ __forceinline__ void mma_f16(float* c, const uint32_t* a,
                                        uint32_t b0, uint32_t b1) {
    asm volatile(
        "mma.sync.aligned.m16n8k16.row.col.f32.f16.f16.f32 "
        "{%0,%1,%2,%3}, {%4,%5,%6,%7}, {%8,%9}, {%0,%1,%2,%3};"
        : "+f"(c[0]), "+f"(c[1]), "+f"(c[2]), "+f"(c[3])
        : "r"(a[0]), "r"(a[1]), "r"(a[2]), "r"(a[3]), "r"(b0), "r"(b1));
}

// ---------------------------------------------------------------------------
// GEMM: C[M,N] = A[M,K] * B[N,K]^T (+bias), fp16 mma.sync, fp32 accumulate.
// CTA tile 128(M) x 128(N) x 64(K); 4 warps (2x2) of 64x64; 3-stage cp.async.
// TWO CTAs per SM; grid x->M so co-resident CTAs share the B slice (L2-hot).
// Output dtype chosen at COMPILE time (OUT_HALF template).
// ---------------------------------------------------------------------------
static constexpr int MT = 128;
static constexpr int NT = 128;
static constexpr int KC = 64;                      // halves of K per chunk (128B/row)
static constexpr int STAGES = 3;
static constexpr int THREADS = 128;
static constexpr int ROWB = 144;                   // padded row stride in bytes
static constexpr int A_BYTES = MT * ROWB;          // 18432
static constexpr int B_BYTES = NT * ROWB;          // 18432
static constexpr int BUF     = A_BYTES + B_BYTES;  // 36864
static constexpr int SMEM_TOTAL = STAGES * BUF;    // 110592 (x2 CTAs = 221184 < 227KB)

__device__ __forceinline__ void load_chunk(uint32_t bufb,
                                           const __half* __restrict__ A,
                                           const __half* __restrict__ Bm,
                                           int mbase, int nbase, int K, int kc, int tid) {
    const int kofs = kc * KC;
#pragma unroll
    for (int i = 0; i < 8; i++) {                  // A: 128 rows x 8 segs / 128 thr
        int j = tid + (i << 7);
        int r = j >> 3, s = j & 7;
        const __half* src = A + (size_t)(mbase + r) * K + kofs + s * 8;
        CP_ASYNC16(bufb + (uint32_t)(r * ROWB + s * 16), src);
    }
#pragma unroll
    for (int i = 0; i < 8; i++) {                  // B: 128 rows x 8 segs / 128 thr
        int j = tid + (i << 7);
        int r = j >> 3, s = j & 7;
        const __half* src = Bm + (size_t)(nbase + r) * K + kofs + s * 8;
        CP_ASYNC16(bufb + (uint32_t)A_BYTES + (uint32_t)(r * ROWB + s * 16), src);
    }
}

// load fragments for one k16 step (4 A tiles m16k16, 4 B tiles n16k16)
__device__ __forceinline__ void load_frags(uint32_t bufb, uint32_t a_lane, uint32_t b_lane,
                                           int ks, uint32_t a[4][4], uint32_t b[4][4]) {
    const uint32_t boff = (uint32_t)(ks * 32);     // 16 halves = 32B per k16 step
#pragma unroll
    for (int mt = 0; mt < 4; mt++)
        ldsm_x4(a[mt], bufb + a_lane + (uint32_t)(mt * 16 * ROWB) + boff);
#pragma unroll
    for (int np = 0; np < 4; np++)
        ldsm_x4(b[np], bufb + b_lane + (uint32_t)(np * 16 * ROWB) + boff);
}

template <bool OUT_HALF>
__global__ void __launch_bounds__(THREADS, 2)
gemm_f16_mma(const __half* __restrict__ A, const __half* __restrict__ Bm,
             const float* __restrict__ bias, float* __restrict__ C,
             __half* __restrict__ Ch, int M, int N, int K) {
    extern __shared__ __align__(16) char smem[];
    const uint32_t sb = smem_u32(smem);
    const int tid = threadIdx.x;
    const int wid = tid >> 5;
    const int l   = tid & 31;
    const int wm  = wid >> 1;          // 0..1  (M warp row, 64 rows each)
    const int wn  = wid & 1;           // 0..1  (N warp col, 64 cols each)
    const int mbase = blockIdx.x * MT; // bx -> M: co-resident CTAs share B slice
    const int nbase = blockIdx.y * NT;

    const int      lrow = (l & 7) + ((l >> 3) & 1) * 8;
    const uint32_t lhi  = (uint32_t)((l >> 4) * 16);
    const uint32_t a_lane = (uint32_t)((wm * 64 + lrow) * ROWB) + lhi;
    const uint32_t b_lane = (uint32_t)A_BYTES + (uint32_t)((wn * 64 + lrow) * ROWB) + lhi;

    float c[4][8][4];
#pragma unroll
    for (int mt = 0; mt < 4; mt++)
#pragma unroll
        for (int nt = 0; nt < 8; nt++)
#pragma unroll
            for (int q = 0; q < 4; q++) c[mt][nt][q] = 0.0f;

    const int nch = K / KC;            // 16 for K=1024

    load_chunk(sb, A, Bm, mbase, nbase, K, 0, tid);
    CP_COMMIT();
    load_chunk(sb + BUF, A, Bm, mbase, nbase, K, 1, tid);
    CP_COMMIT();

    uint32_t afr[2][4][4], bfr[2][4][4];
    uint32_t slot = 0;
    for (int kc = 0; kc < nch; kc++) {
        CP_WAIT1();
        __syncthreads();
        const uint32_t bufb = sb + slot * BUF;
        if (kc + 2 < nch) {
            uint32_t ws = slot + 2; if (ws >= STAGES) ws -= STAGES;
            load_chunk(sb + ws * BUF, A, Bm, mbase, nbase, K, kc + 2, tid);
        }
        CP_COMMIT();

        load_frags(bufb, a_lane, b_lane, 0, afr[0], bfr[0]);
#pragma unroll
        for (int ks = 0; ks < 4; ks++) {           // 4 x k16 = K chunk of 64
            const int cur = ks & 1;
            if (ks < 3)
                load_frags(bufb, a_lane, b_lane, ks + 1, afr[cur ^ 1], bfr[cur ^ 1]);
#pragma unroll
            for (int mt = 0; mt < 4; mt++)
#pragma unroll
                for (int nt = 0; nt < 8; nt++) {
                    const int np = nt >> 1, od = nt & 1;
                    mma_f16(c[mt][nt], afr[cur][mt], bfr[cur][np][od], bfr[cur][np][2 + od]);
                }
        }
        slot++; if (slot >= STAGES) slot = 0;
    }

    // Epilogue: rows = mbase+wm*64+mt*16+{g,g+8}, cols = nbase+wn*64+nt*8+2t+{0,1}
    const int g = l >> 2, t = l & 3;
    const int row0 = mbase + wm * 64 + g;
    const int colb = nbase + wn * 64 + t * 2;
#pragma unroll
    for (int nt = 0; nt < 8; nt++) {
        float2 bv = make_float2(0.0f, 0.0f);
        if (bias) bv = *reinterpret_cast<const float2*>(bias + colb + nt * 8);
#pragma unroll
        for (int mt = 0; mt < 4; mt++) {
            const int r = row0 + mt * 16;
            float2 v0 = make_float2(c[mt][nt][0] + bv.x, c[mt][nt][1] + bv.y);
            float2 v1 = make_float2(c[mt][nt][2] + bv.x, c[mt][nt][3] + bv.y);
            if (OUT_HALF) {
                *reinterpret_cast<__half2*>(Ch + (size_t)r * N + colb + nt * 8)
                    = __floats2half2_rn(v0.x, v0.y);
                *reinterpret_cast<__half2*>(Ch + (size_t)(r + 8) * N + colb + nt * 8)
                    = __floats2half2_rn(v1.x, v1.y);
            } else {
                *reinterpret_cast<float2*>(C + (size_t)r * N + colb + nt * 8)       = v0;
                *reinterpret_cast<float2*>(C + (size_t)(r + 8) * N + colb + nt * 8) = v1;
            }
        }
    }
}

// ---------------------------------------------------------------------------
// Small kernels
// ---------------------------------------------------------------------------
__global__ void detect_kernel(const void* seq) {
    __shared__ int ok;
    if (threadIdx.x == 0) ok = 1;
    __syncthreads();
    const long long* p = (const long long*)seq;   // reads 16KB <= int32 buffer size
    for (int i = threadIdx.x; i < MROWS / 2; i += blockDim.x) {
        long long v = p[i];
        if (v < 0 || v >= VOCAB) ok = 0;
    }
    __syncthreads();
    if (threadIdx.x == 0) g_is64 = ok;
}

__device__ __forceinline__ long long get_tok(const void* seq, int idx) {
    if (g_is64) return ((const long long*)seq)[idx];
    return (long long)((const int*)seq)[idx];
}

// fp32 weights -> fp16 (round-to-nearest); 2 float4 per thread for MLP
__global__ void cvt_kernel(const float* __restrict__ src, __half* __restrict__ dst) {
    const size_t i0 = ((size_t)blockIdx.x * blockDim.x + threadIdx.x) * 2;
    float4 v0 = reinterpret_cast<const float4*>(src)[i0];
    float4 v1 = reinterpret_cast<const float4*>(src)[i0 + 1];
    __half2 h[4];
    h[0] = __floats2half2_rn(v0.x, v0.y);
    h[1] = __floats2half2_rn(v0.z, v0.w);
    h[2] = __floats2half2_rn(v1.x, v1.y);
    h[3] = __floats2half2_rn(v1.z, v1.w);
    reinterpret_cast<float4*>(dst)[i0 >> 1] = *reinterpret_cast<float4*>(h);
}

// --- fused gather + causal cumulative mean over EMBEDDINGS (scan-first) ----
// Grids split BOTH (b,seg) and the dim axis (DCH chunks of 512 dims, float2
// lanes) -> 512 blocks x 256 thr: ~2x occupancy vs float4/256-block version.
// pass 1: per-(b,seg) sums of gathered embedding rows (fp32)
__global__ void segsum_emb(const void* __restrict__ seq, const float* __restrict__ emb,
                           float* __restrict__ S) {
    const int bs   = blockIdx.x >> 1;             // (b*SEGS+seg)
    const int b    = bs / SEGS;
    const int seg  = bs % SEGS;
    const int d    = (blockIdx.x & 1) * (DIMS / DCH) + threadIdx.x * 2;
    const int lbase = b * LL + seg * SEGL;
    float2 acc = make_float2(0.f, 0.f);
#pragma unroll
    for (int lq = 0; lq < SEGL; lq++) {
        const long long tok = get_tok(seq, lbase + lq);
        float2 v = *reinterpret_cast<const float2*>(emb + (size_t)tok * DIMS + d);
        acc.x += v.x; acc.y += v.y;
    }
    *reinterpret_cast<float2*>(S + (size_t)bs * DIMS + d) = acc;
}

// pass 2: prefix of segment sums (4-way MLP) + in-segment running mean -> fp16
__global__ void cummean_emb(const void* __restrict__ seq, const float* __restrict__ emb,
                            const float* __restrict__ S, __half* __restrict__ eavg) {
    const int bs   = blockIdx.x >> 1;
    const int b    = bs / SEGS;
    const int seg  = bs % SEGS;
    const int d    = (blockIdx.x & 1) * (DIMS / DCH) + threadIdx.x * 2;
    // 4 independent accumulators over the prefix for memory-level parallelism
    float2 a0 = make_float2(0.f, 0.f);
    float2 a1 = a0, a2 = a0, a3 = a0;
    const float* Sp = S + (size_t)b * SEGS * DIMS + d;
    int j = 0;
    for (; j + 4 <= seg; j += 4) {
        float2 s0 = *reinterpret_cast<const float2*>(Sp + (size_t)(j + 0) * DIMS);
        float2 s1 = *reinterpret_cast<const float2*>(Sp + (size_t)(j + 1) * DIMS);
        float2 s2 = *reinterpret_cast<const float2*>(Sp + (size_t)(j + 2) * DIMS);
        float2 s3 = *reinterpret_cast<const float2*>(Sp + (size_t)(j + 3) * DIMS);
        a0.x += s0.x; a0.y += s0.y;
        a1.x += s1.x; a1.y += s1.y;
        a2.x += s2.x; a2.y += s2.y;
        a3.x += s3.x; a3.y += s3.y;
    }
    for (; j < seg; j++) {
        float2 s0 = *reinterpret_cast<const float2*>(Sp + (size_t)j * DIMS);
        a0.x += s0.x; a0.y += s0.y;
    }
    float2 acc;
    acc.x = (a0.x + a1.x) + (a2.x + a3.x);
    acc.y = (a0.y + a1.y) + (a2.y + a3.y);

    const int lbase = b * LL + seg * SEGL;
    __half* ap = eavg + (size_t)lbase * DIMS + d;
#pragma unroll
    for (int lq = 0; lq < SEGL; lq++) {
        const long long tok = get_tok(seq, lbase + lq);
        float2 v = *reinterpret_cast<const float2*>(emb + (size_t)tok * DIMS + d);
        acc.x += v.x; acc.y += v.y;
        const float inv = 1.0f / (float)(seg * SEGL + lq + 1);
        *reinterpret_cast<__half2*>(ap + (size_t)lq * DIMS)
            = __floats2half2_rn(acc.x * inv, acc.y * inv);
    }
}

// ---------------------------------------------------------------------------
// Launch
// ---------------------------------------------------------------------------
extern "C" void kernel_launch(void* const* d_in, const int* in_sizes, int n_in,
                              void* d_out, int out_size) {
    const void*  seq = d_in[0];
    const float* emb = (const float*)d_in[1];
    const float* WV  = (const float*)d_in[2];
    const float* WO  = (const float*)d_in[3];
    const float* bo  = (const float*)d_in[4];
    float* out = (float*)d_out;

    cudaFuncSetAttribute(gemm_f16_mma<false>,
                         cudaFuncAttributeMaxDynamicSharedMemorySize, SMEM_TOTAL);
    cudaFuncSetAttribute(gemm_f16_mma<true>,
                         cudaFuncAttributeMaxDynamicSharedMemorySize, SMEM_TOTAL);

    __half *gea, *ga, *gwv, *gwo;
    float *gs;
    cudaGetSymbolAddress((void**)&gea, g_eavg);
    cudaGetSymbolAddress((void**)&ga,  g_avg);
    cudaGetSymbolAddress((void**)&gwv, g_wv);
    cudaGetSymbolAddress((void**)&gwo, g_wo);
    cudaGetSymbolAddress((void**)&gs,  g_seg);

    detect_kernel<<<1, 256>>>(seq);
    cvt_kernel<<<(DIMS * DIMS) / 8 / 256, 256>>>(WV, gwv);
    cvt_kernel<<<(VOCAB * DIMS) / 8 / 256, 256>>>(WO, gwo);

    // scan-first: cummean(e) directly from gathered embeddings (512-block grids)
    segsum_emb<<<BB * SEGS * DCH, 256>>>(seq, emb, gs);
    cummean_emb<<<BB * SEGS * DCH, 256>>>(seq, emb, gs, gea);

    // GEMM1: avg = cummean(e) @ W_V^T   [4096 x 1024 x 1024], fp16 output
    gemm_f16_mma<true><<<dim3(MROWS / MT, DIMS / NT), THREADS, SMEM_TOTAL>>>(
        gea, gwv, nullptr, nullptr, ga, MROWS, DIMS, DIMS);

    // GEMM2: out = avg @ W_out^T + b   [4096 x 32000 x 1024], fp32 output
    gemm_f16_mma<false><<<dim3(MROWS / MT, VOCAB / NT), THREADS, SMEM_TOTAL>>>(
        ga, gwo, bo, out, nullptr, MROWS, VOCAB, DIMS);
}